// round 6
// baseline (speedup 1.0000x reference)
#include <cuda_runtime.h>
#include <math.h>
#include <cstdint>

#define NTOK 8192      // B*S
#define DIM  1024      // d_model
#define NE   8         // experts
#define TOPK 2
#define HID  4096      // expert hidden
#define NA   (NTOK*TOPK)   // 16384 assignments
#define CAP  NA            // per-expert bucket capacity (worst case)

// ---------------- device scratch (no allocations allowed) ----------------
__device__ int   g_bucket[NE*CAP];
__device__ int   g_cursor[NE];
__device__ float g_prob_sum[NE];
__device__ float g_topk_w[NA];
__device__ float g_h[(size_t)NA*HID];       // up-proj activations (268 MB), tf32-rounded
__device__ float g_y[(size_t)NA*DIM];       // down-proj outputs   (67 MB)
__device__ float g_xr[(size_t)NTOK*DIM];    // tf32-rounded x      (33 MB)
__device__ float g_wur[(size_t)NE*DIM*HID]; // tf32-rounded w_up   (134 MB)
__device__ float g_wdr[(size_t)NE*HID*DIM]; // tf32-rounded w_down (134 MB)

__device__ __forceinline__ uint32_t f2tf32(float f) {
    uint32_t r;
    asm("cvt.rna.tf32.f32 %0, %1;" : "=r"(r) : "f"(f));
    return r;
}

// ---------------- tf32 pre-round (one cvt per element, outside GEMM) ------
__global__ __launch_bounds__(256) void round_kernel(
    const float4* __restrict__ src, float4* __restrict__ dst, int n4)
{
    int stride = gridDim.x * blockDim.x;
    for (int i = blockIdx.x * blockDim.x + threadIdx.x; i < n4; i += stride) {
        float4 v = src[i];
        v.x = __uint_as_float(f2tf32(v.x));
        v.y = __uint_as_float(f2tf32(v.y));
        v.z = __uint_as_float(f2tf32(v.z));
        v.w = __uint_as_float(f2tf32(v.w));
        dst[i] = v;
    }
}

// ---------------- kernel 1: zero accumulators ----------------
__global__ void zero_kernel() {
    int t = threadIdx.x;
    if (t < NE) { g_cursor[t] = 0; g_prob_sum[t] = 0.f; }
}

// ---------------- kernel 2: router ----------------
__global__ __launch_bounds__(256) void router_kernel(
    const float* __restrict__ x, const float* __restrict__ rw,
    const float* __restrict__ rb, float* __restrict__ probs_out)
{
    int t   = blockIdx.x;
    int tid = threadIdx.x;
    const float* xr = x + (size_t)t * DIM;

    float acc[NE];
    #pragma unroll
    for (int e = 0; e < NE; e++) acc[e] = 0.f;

    for (int d = tid; d < DIM; d += 256) {
        float xv = xr[d];
        const float* w = rw + (size_t)d * NE;
        #pragma unroll
        for (int e = 0; e < NE; e++) acc[e] += xv * w[e];
    }
    #pragma unroll
    for (int e = 0; e < NE; e++) {
        #pragma unroll
        for (int off = 16; off > 0; off >>= 1)
            acc[e] += __shfl_down_sync(0xffffffffu, acc[e], off);
    }
    __shared__ float wsum[8][NE];
    int warp = tid >> 5, lane = tid & 31;
    if (lane == 0) {
        #pragma unroll
        for (int e = 0; e < NE; e++) wsum[warp][e] = acc[e];
    }
    __syncthreads();

    if (tid == 0) {
        float lg[NE];
        #pragma unroll
        for (int e = 0; e < NE; e++) {
            float s = rb[e];
            #pragma unroll
            for (int w = 0; w < 8; w++) s += wsum[w][e];
            lg[e] = s;
        }
        float mx = lg[0];
        #pragma unroll
        for (int e = 1; e < NE; e++) mx = fmaxf(mx, lg[e]);
        float p[NE], den = 0.f;
        #pragma unroll
        for (int e = 0; e < NE; e++) { p[e] = expf(lg[e] - mx); den += p[e]; }
        float inv = 1.f / den;
        #pragma unroll
        for (int e = 0; e < NE; e++) {
            p[e] *= inv;
            probs_out[(size_t)t * NE + e] = p[e];
            atomicAdd(&g_prob_sum[e], p[e]);
        }
        int i0 = 0;
        #pragma unroll
        for (int e = 1; e < NE; e++) if (lg[e] > lg[i0]) i0 = e;
        int i1 = -1;
        #pragma unroll
        for (int e = 0; e < NE; e++)
            if (e != i0 && (i1 < 0 || lg[e] > lg[i1])) i1 = e;
        float e1 = expf(lg[i1] - lg[i0]);
        float p0 = 1.f / (1.f + e1);
        float p1 = e1 * p0;

        int a0 = t * TOPK + 0, a1 = t * TOPK + 1;
        g_topk_w[a0] = p0;
        g_topk_w[a1] = p1;
        int s0 = atomicAdd(&g_cursor[i0], 1);
        g_bucket[i0 * CAP + s0] = a0;
        int s1 = atomicAdd(&g_cursor[i1], 1);
        g_bucket[i1 * CAP + s1] = a1;
    }
}

// ---------------- kernel 3: aux loss ----------------
__global__ void aux_kernel(float* __restrict__ out_aux) {
    if (threadIdx.x == 0) {
        float s = 0.f;
        #pragma unroll
        for (int e = 0; e < NE; e++)
            s += ((float)g_cursor[e] / (float)NA) * (g_prob_sum[e] / (float)NTOK);
        *out_aux = (float)NE * s * 0.01f;
    }
}

// ---------------- tensor-core grouped GEMM ----------------
// 256 threads (8 warps, 4x2 grid of 32x64 warp tiles), register
// double-buffered fragments so LDS(k8+1) overlaps mma(k8).
#define TM 128
#define TN 128
#define TKK 32
#define STAGES 3
#define A_STRIDE (TKK+4)     // A tile [m][k]
#define B_STRIDE (TN+8)      // B tile [k][n]
#define SMEM_FLOATS (STAGES*(TM*A_STRIDE + TKK*B_STRIDE))
#define SMEM_BYTES (SMEM_FLOATS*4 + TM*4)

__device__ __forceinline__ float gelu_tanh(float v) {
    float c = v * v * v;
    return 0.5f * v * (1.f + tanhf(0.7978845608028654f * (v + 0.044715f * c)));
}

__device__ __forceinline__ void mma_tf32(float* c, const uint32_t* a, const uint32_t* b) {
    asm volatile(
        "mma.sync.aligned.m16n8k8.row.col.f32.tf32.tf32.f32 "
        "{%0,%1,%2,%3}, {%4,%5,%6,%7}, {%8,%9}, {%0,%1,%2,%3};"
        : "+f"(c[0]), "+f"(c[1]), "+f"(c[2]), "+f"(c[3])
        : "r"(a[0]), "r"(a[1]), "r"(a[2]), "r"(a[3]), "r"(b[0]), "r"(b[1]));
}

__device__ __forceinline__ void cp_async16(float* dst, const float* src, bool pred) {
    uint32_t d = (uint32_t)__cvta_generic_to_shared(dst);
    int sz = pred ? 16 : 0;
    asm volatile("cp.async.cg.shared.global [%0], [%1], 16, %2;\n"
                 :: "r"(d), "l"(src), "r"(sz));
}

// UP:  A = gathered g_xr rows, W = g_wur[e] (DIM x HID), epilogue = gelu+round -> g_h
// DN:  A = gathered g_h rows,  W = g_wdr[e] (HID x DIM), epilogue = +bias -> g_y
template<bool UP>
__global__ __launch_bounds__(256, 1)
void mma_gemm_kernel(const float* __restrict__ Ball)
{
    constexpr int KD = UP ? DIM : HID;
    constexpr int ND = UP ? HID : DIM;
    constexpr int KT = KD / TKK;

    int e   = blockIdx.z;
    int cnt = g_cursor[e];
    int m0  = blockIdx.y * TM;
    if (m0 >= cnt) return;
    int n0  = blockIdx.x * TN;

    extern __shared__ float smem[];
    float* As = smem;                                   // [STAGES][TM][A_STRIDE]
    float* Bs = smem + STAGES * TM * A_STRIDE;          // [STAGES][TKK][B_STRIDE]
    int*  rows = (int*)(Bs + STAGES * TKK * B_STRIDE);  // [TM]

    int tid = threadIdx.x;
    if (tid < TM) {
        int m = m0 + tid;
        rows[tid] = (m < cnt) ? g_bucket[e * CAP + m] : -1;
    }
    __syncthreads();

    const float* W = (UP ? g_wur : g_wdr) + (size_t)e * KD * ND;
    const float* Abase = UP ? (const float*)g_xr : (const float*)g_h;

    auto issue = [&](int kt, int stage) {
        float* as = As + stage * TM * A_STRIDE;
        float* bs = Bs + stage * TKK * B_STRIDE;
        int kbase = kt * TKK;
        #pragma unroll
        for (int i = 0; i < 4; i++) {
            int c = tid + i * 256;
            int r = c >> 3, q = c & 7;      // 128 rows x 8 float4 chunks
            int a = rows[r];
            bool pred = (a >= 0);
            const float* src;
            if (UP) src = Abase + (size_t)(pred ? (a >> 1) : 0) * DIM + kbase + q * 4;
            else    src = Abase + (size_t)(pred ? a : 0) * HID + kbase + q * 4;
            cp_async16(as + r * A_STRIDE + q * 4, src, pred);
        }
        #pragma unroll
        for (int i = 0; i < 4; i++) {
            int c = tid + i * 256;
            int k = c >> 5, q = c & 31;     // 32 k-rows x 32 float4 chunks
            cp_async16(bs + k * B_STRIDE + q * 4,
                       W + (size_t)(kbase + k) * ND + n0 + q * 4, true);
        }
    };

    #pragma unroll
    for (int s = 0; s < STAGES - 1; s++) {
        if (s < KT) issue(s, s);
        asm volatile("cp.async.commit_group;");
    }

    int wid = tid >> 5, lane = tid & 31;
    int g = lane >> 2, t = lane & 3;
    int wm = (wid >> 1) * 32;   // 4x2 warp grid, 32x64 warp tiles
    int wn = (wid & 1) * 64;

    float acc[2][8][4];
    #pragma unroll
    for (int i = 0; i < 2; i++)
        #pragma unroll
        for (int j = 0; j < 8; j++)
            #pragma unroll
            for (int q = 0; q < 4; q++) acc[i][j][q] = 0.f;

    for (int kt = 0; kt < KT; kt++) {
        asm volatile("cp.async.wait_group %0;" :: "n"(STAGES - 2));
        __syncthreads();

        int nstage = kt + STAGES - 1;
        if (nstage < KT) issue(nstage, nstage % STAGES);
        asm volatile("cp.async.commit_group;");

        const uint32_t* as = (const uint32_t*)(As + (kt % STAGES) * TM * A_STRIDE);
        const uint32_t* bs = (const uint32_t*)(Bs + (kt % STAGES) * TKK * B_STRIDE);

        // register double-buffered fragments: LDS(k8+1) overlaps mma(k8)
        uint32_t af[2][2][4], bf[2][8][2];

        auto load_frag = [&](int k8, uint32_t afr[2][4], uint32_t bfr[8][2]) {
            #pragma unroll
            for (int i = 0; i < 2; i++) {
                int mrow = wm + i * 16;
                afr[i][0] = as[(mrow + g    ) * A_STRIDE + k8 * 8 + t];
                afr[i][1] = as[(mrow + g + 8) * A_STRIDE + k8 * 8 + t];
                afr[i][2] = as[(mrow + g    ) * A_STRIDE + k8 * 8 + t + 4];
                afr[i][3] = as[(mrow + g + 8) * A_STRIDE + k8 * 8 + t + 4];
            }
            #pragma unroll
            for (int j = 0; j < 8; j++) {
                int ncol = wn + j * 8 + g;
                bfr[j][0] = bs[(k8 * 8 + t    ) * B_STRIDE + ncol];
                bfr[j][1] = bs[(k8 * 8 + t + 4) * B_STRIDE + ncol];
            }
        };

        load_frag(0, af[0], bf[0]);
        #pragma unroll
        for (int k8 = 0; k8 < TKK / 8; k8++) {
            int cur = k8 & 1, nxt = cur ^ 1;
            if (k8 < TKK / 8 - 1) load_frag(k8 + 1, af[nxt], bf[nxt]);
            #pragma unroll
            for (int i = 0; i < 2; i++)
                #pragma unroll
                for (int j = 0; j < 8; j++)
                    mma_tf32(acc[i][j], af[cur][i], bf[cur][j]);
        }
    }

    // epilogue: bias (+gelu, +tf32 round for UP) and scatter by assignment id
    const float* bb = Ball + (size_t)e * ND + n0;
    #pragma unroll
    for (int i = 0; i < 2; i++) {
        int r0 = wm + i * 16 + g;
        int r1 = r0 + 8;
        int a0 = rows[r0], a1 = rows[r1];
        float* d0 = (a0 >= 0) ? ((UP ? g_h + (size_t)a0 * HID : g_y + (size_t)a0 * DIM) + n0) : nullptr;
        float* d1 = (a1 >= 0) ? ((UP ? g_h + (size_t)a1 * HID : g_y + (size_t)a1 * DIM) + n0) : nullptr;
        #pragma unroll
        for (int j = 0; j < 8; j++) {
            int col = wn + j * 8 + t * 2;
            float bx = bb[col], by = bb[col + 1];
            if (d0) {
                float v0 = acc[i][j][0] + bx, v1 = acc[i][j][1] + by;
                if (UP) {
                    v0 = __uint_as_float(f2tf32(gelu_tanh(v0)));
                    v1 = __uint_as_float(f2tf32(gelu_tanh(v1)));
                }
                *(float2*)(d0 + col) = make_float2(v0, v1);
            }
            if (d1) {
                float v2 = acc[i][j][2] + bx, v3 = acc[i][j][3] + by;
                if (UP) {
                    v2 = __uint_as_float(f2tf32(gelu_tanh(v2)));
                    v3 = __uint_as_float(f2tf32(gelu_tanh(v3)));
                }
                *(float2*)(d1 + col) = make_float2(v2, v3);
            }
        }
    }
}

// ---------------- kernel 6: deterministic weighted combine ----------------
__global__ __launch_bounds__(256) void combine_kernel(float* __restrict__ out) {
    int t = blockIdx.x;
    float w0 = g_topk_w[t * TOPK + 0];
    float w1 = g_topk_w[t * TOPK + 1];
    const float4* y0 = (const float4*)(g_y + (size_t)(t * TOPK + 0) * DIM);
    const float4* y1 = (const float4*)(g_y + (size_t)(t * TOPK + 1) * DIM);
    float4* o = (float4*)(out + (size_t)t * DIM);
    for (int d = threadIdx.x; d < DIM / 4; d += 256) {
        float4 a = y0[d], b = y1[d];
        float4 r;
        r.x = w0 * a.x + w1 * b.x;
        r.y = w0 * a.y + w1 * b.y;
        r.z = w0 * a.z + w1 * b.z;
        r.w = w0 * a.w + w1 * b.w;
        o[d] = r;
    }
}

// ---------------- launch ----------------
extern "C" void kernel_launch(void* const* d_in, const int* in_sizes, int n_in,
                              void* d_out, int out_size)
{
    const float* x  = (const float*)d_in[0];
    const float* rw = (const float*)d_in[1];
    const float* rb = (const float*)d_in[2];
    const float* wu = (const float*)d_in[3];
    const float* bu = (const float*)d_in[4];
    const float* wd = (const float*)d_in[5];
    const float* bd = (const float*)d_in[6];

    float* out       = (float*)d_out;
    float* out_y     = out;
    float* out_aux   = out + (size_t)NTOK * DIM;
    float* out_probs = out_aux + 1;

    cudaFuncSetAttribute(mma_gemm_kernel<true>,
        cudaFuncAttributeMaxDynamicSharedMemorySize, SMEM_BYTES);
    cudaFuncSetAttribute(mma_gemm_kernel<false>,
        cudaFuncAttributeMaxDynamicSharedMemorySize, SMEM_BYTES);

    float* d_xr  = nullptr; cudaGetSymbolAddress((void**)&d_xr,  g_xr);
    float* d_wur = nullptr; cudaGetSymbolAddress((void**)&d_wur, g_wur);
    float* d_wdr = nullptr; cudaGetSymbolAddress((void**)&d_wdr, g_wdr);

    zero_kernel<<<1, 32>>>();
    router_kernel<<<NTOK, 256>>>(x, rw, rb, out_probs);
    aux_kernel<<<1, 32>>>(out_aux);

    // tf32 pre-round (one-time cvt per element)
    round_kernel<<<1184, 256>>>((const float4*)x,  (float4*)d_xr,  NTOK * DIM / 4);
    round_kernel<<<2368, 256>>>((const float4*)wu, (float4*)d_wur, NE * DIM * HID / 4);
    round_kernel<<<2368, 256>>>((const float4*)wd, (float4*)d_wdr, NE * HID * DIM / 4);

    dim3 gu(HID / TN, CAP / TM, NE);
    mma_gemm_kernel<true><<<gu, 256, SMEM_BYTES>>>(bu);

    dim3 gd(DIM / TN, CAP / TM, NE);
    mma_gemm_kernel<false><<<gd, 256, SMEM_BYTES>>>(bd);

    combine_kernel<<<NTOK, 256>>>(out_y);
}

// round 7
// speedup vs baseline: 1.4109x; 1.4109x over previous
#include <cuda_runtime.h>
#include <cuda_fp16.h>
#include <math.h>
#include <cstdint>

#define NTOK 8192      // B*S
#define DIM  1024      // d_model
#define NE   8         // experts
#define TOPK 2
#define HID  4096      // expert hidden
#define NA   (NTOK*TOPK)   // 16384 assignments
#define CAP  NA            // per-expert bucket capacity (worst case)

// ---------------- device scratch (no allocations allowed) ----------------
__device__ int    g_bucket[NE*CAP];
__device__ int    g_cursor[NE];
__device__ float  g_prob_sum[NE];
__device__ float  g_topk_w[NA];
__device__ float  g_y[(size_t)NA*DIM];            // 67 MB
__device__ __half g_xh[(size_t)NTOK*DIM];         // fp16 x, 16.8 MB
__device__ __half g_wuh[(size_t)NE*HID*DIM];      // fp16 w_up^T  [e][n][k], 67 MB
__device__ __half g_wdh[(size_t)NE*DIM*HID];      // fp16 w_down^T[e][n][k], 67 MB
__device__ __half g_hh[(size_t)NA*HID];           // fp16 activations, 134 MB

// ---------------- kernel: zero ----------------
__global__ void zero_kernel() {
    int t = threadIdx.x;
    if (t < NE) { g_cursor[t] = 0; g_prob_sum[t] = 0.f; }
}

// ---------------- kernel: router ----------------
__global__ __launch_bounds__(256) void router_kernel(
    const float* __restrict__ x, const float* __restrict__ rw,
    const float* __restrict__ rb, float* __restrict__ probs_out)
{
    int t   = blockIdx.x;
    int tid = threadIdx.x;
    const float* xr = x + (size_t)t * DIM;

    float acc[NE];
    #pragma unroll
    for (int e = 0; e < NE; e++) acc[e] = 0.f;

    for (int d = tid; d < DIM; d += 256) {
        float xv = xr[d];
        const float* w = rw + (size_t)d * NE;
        #pragma unroll
        for (int e = 0; e < NE; e++) acc[e] += xv * w[e];
    }
    #pragma unroll
    for (int e = 0; e < NE; e++) {
        #pragma unroll
        for (int off = 16; off > 0; off >>= 1)
            acc[e] += __shfl_down_sync(0xffffffffu, acc[e], off);
    }
    __shared__ float wsum[8][NE];
    int warp = tid >> 5, lane = tid & 31;
    if (lane == 0) {
        #pragma unroll
        for (int e = 0; e < NE; e++) wsum[warp][e] = acc[e];
    }
    __syncthreads();

    if (tid == 0) {
        float lg[NE];
        #pragma unroll
        for (int e = 0; e < NE; e++) {
            float s = rb[e];
            #pragma unroll
            for (int w = 0; w < 8; w++) s += wsum[w][e];
            lg[e] = s;
        }
        float mx = lg[0];
        #pragma unroll
        for (int e = 1; e < NE; e++) mx = fmaxf(mx, lg[e]);
        float p[NE], den = 0.f;
        #pragma unroll
        for (int e = 0; e < NE; e++) { p[e] = expf(lg[e] - mx); den += p[e]; }
        float inv = 1.f / den;
        #pragma unroll
        for (int e = 0; e < NE; e++) {
            p[e] *= inv;
            probs_out[(size_t)t * NE + e] = p[e];
            atomicAdd(&g_prob_sum[e], p[e]);
        }
        int i0 = 0;
        #pragma unroll
        for (int e = 1; e < NE; e++) if (lg[e] > lg[i0]) i0 = e;
        int i1 = -1;
        #pragma unroll
        for (int e = 0; e < NE; e++)
            if (e != i0 && (i1 < 0 || lg[e] > lg[i1])) i1 = e;
        float e1 = expf(lg[i1] - lg[i0]);
        float p0 = 1.f / (1.f + e1);
        float p1 = e1 * p0;

        int a0 = t * TOPK + 0, a1 = t * TOPK + 1;
        g_topk_w[a0] = p0;
        g_topk_w[a1] = p1;
        int s0 = atomicAdd(&g_cursor[i0], 1);
        g_bucket[i0 * CAP + s0] = a0;
        int s1 = atomicAdd(&g_cursor[i1], 1);
        g_bucket[i1 * CAP + s1] = a1;
    }
}

// ---------------- kernel: aux loss ----------------
__global__ void aux_kernel(float* __restrict__ out_aux) {
    if (threadIdx.x == 0) {
        float s = 0.f;
        #pragma unroll
        for (int e = 0; e < NE; e++)
            s += ((float)g_cursor[e] / (float)NA) * (g_prob_sum[e] / (float)NTOK);
        *out_aux = (float)NE * s * 0.01f;
    }
}

// ---------------- kernel: convert x to fp16 ----------------
__global__ __launch_bounds__(256) void cvt_x_kernel(const float4* __restrict__ src, int n4) {
    int stride = gridDim.x * blockDim.x;
    for (int i = blockIdx.x * blockDim.x + threadIdx.x; i < n4; i += stride) {
        float4 v = src[i];
        __half2 h01 = __floats2half2_rn(v.x, v.y);
        __half2 h23 = __floats2half2_rn(v.z, v.w);
        ((uint2*)g_xh)[i] = make_uint2(*(uint32_t*)&h01, *(uint32_t*)&h23);
    }
}

// ---------------- kernel: transpose + convert weights to fp16 ----------------
// W [E][KD][ND] fp32 -> Wt [E][ND][KD] fp16
template<int KD, int ND>
__global__ __launch_bounds__(256) void trans_cvt_kernel(
    const float* __restrict__ W, __half* __restrict__ Wt)
{
    __shared__ float tile[32][33];
    int e  = blockIdx.z;
    int n0 = blockIdx.x * 32;
    int k0 = blockIdx.y * 32;
    int tx = threadIdx.x & 31, ty = threadIdx.x >> 5;
    const float* src = W + (size_t)e * KD * ND;
    #pragma unroll
    for (int i = ty; i < 32; i += 8)
        tile[i][tx] = src[(size_t)(k0 + i) * ND + n0 + tx];
    __syncthreads();
    __half* dst = Wt + (size_t)e * ND * KD;
    #pragma unroll
    for (int i = ty; i < 32; i += 8)
        dst[(size_t)(n0 + i) * KD + k0 + tx] = __float2half(tile[tx][i]);
}

// ---------------- fp16 tensor-core grouped GEMM ----------------
// 256 threads, 8 warps (4x2 grid of 32x64 warp tiles), m16n8k16 fp16 mma.
// Tiles: A [TM][40] fp16, B [TN][40] fp16 (n-major weights), 3-stage cp.async.
#define TM 128
#define TN 128
#define TKK 32
#define STAGES 3
#define T_STRIDE 40    // fp16 elems per row (80B = 5 x 16B chunks), conflict-free
#define TILE_H (TM*T_STRIDE)   // fp16 per A (or B) tile
#define STAGE_H (2*TILE_H)
#define SMEM_BYTES (STAGES*STAGE_H*2 + TM*4)

__device__ __forceinline__ float gelu_tanh(float v) {
    float c = v * v * v;
    return 0.5f * v * (1.f + tanhf(0.7978845608028654f * (v + 0.044715f * c)));
}

__device__ __forceinline__ void mma_f16(float* c, const uint32_t* a, const uint32_t* b) {
    asm volatile(
        "mma.sync.aligned.m16n8k16.row.col.f32.f16.f16.f32 "
        "{%0,%1,%2,%3}, {%4,%5,%6,%7}, {%8,%9}, {%0,%1,%2,%3};"
        : "+f"(c[0]), "+f"(c[1]), "+f"(c[2]), "+f"(c[3])
        : "r"(a[0]), "r"(a[1]), "r"(a[2]), "r"(a[3]), "r"(b[0]), "r"(b[1]));
}

__device__ __forceinline__ void cp_async16(void* dst, const void* src, bool pred) {
    uint32_t d = (uint32_t)__cvta_generic_to_shared(dst);
    int sz = pred ? 16 : 0;
    asm volatile("cp.async.cg.shared.global [%0], [%1], 16, %2;\n"
                 :: "r"(d), "l"(src), "r"(sz));
}

// UP:  A = gathered g_xh rows, B = g_wuh[e] [HID][DIM], epilogue = gelu -> g_hh (fp16)
// DN:  A = gathered g_hh rows, B = g_wdh[e] [DIM][HID], epilogue = +bias -> g_y (fp32)
template<bool UP>
__global__ __launch_bounds__(256, 1)
void mma_gemm_kernel(const float* __restrict__ Ball)
{
    constexpr int KD = UP ? DIM : HID;
    constexpr int ND = UP ? HID : DIM;
    constexpr int KT = KD / TKK;

    int e   = blockIdx.z;
    int cnt = g_cursor[e];
    int m0  = blockIdx.y * TM;
    if (m0 >= cnt) return;
    int n0  = blockIdx.x * TN;

    extern __shared__ __half smem[];
    __half* As = smem;                         // [STAGES][TM][T_STRIDE]
    __half* Bs = smem + STAGES * TILE_H;       // [STAGES][TN][T_STRIDE]
    int*   rows = (int*)(smem + 2 * STAGES * TILE_H);

    int tid = threadIdx.x;
    if (tid < TM) {
        int m = m0 + tid;
        rows[tid] = (m < cnt) ? g_bucket[e * CAP + m] : -1;
    }
    __syncthreads();

    const __half* W = (UP ? g_wuh : g_wdh) + (size_t)e * (size_t)ND * KD;
    const __half* Abase = UP ? (const __half*)g_xh : (const __half*)g_hh;

    auto issue = [&](int kt, int stage) {
        __half* as = As + stage * TILE_H;
        __half* bs = Bs + stage * TILE_H;
        int kbase = kt * TKK;
        #pragma unroll
        for (int i = 0; i < 2; i++) {          // A: 128 rows x 4 chunks of 16B
            int c = tid + i * 256;
            int r = c >> 2, q = c & 3;
            int a = rows[r];
            bool pred = (a >= 0);
            const __half* src = Abase +
                (UP ? (size_t)(pred ? (a >> 1) : 0) * DIM
                    : (size_t)(pred ? a : 0) * HID) + kbase + q * 8;
            cp_async16(as + r * T_STRIDE + q * 8, src, pred);
        }
        #pragma unroll
        for (int i = 0; i < 2; i++) {          // B: 128 n-rows x 4 chunks
            int c = tid + i * 256;
            int r = c >> 2, q = c & 3;
            cp_async16(bs + r * T_STRIDE + q * 8,
                       W + (size_t)(n0 + r) * KD + kbase + q * 8, true);
        }
    };

    #pragma unroll
    for (int s = 0; s < STAGES - 1; s++) {
        if (s < KT) issue(s, s);
        asm volatile("cp.async.commit_group;");
    }

    int wid = tid >> 5, lane = tid & 31;
    int g = lane >> 2, t = lane & 3;
    int wm = (wid >> 1) * 32;   // 4x2 warp grid, 32x64 warp tiles
    int wn = (wid & 1) * 64;

    float acc[2][8][4];
    #pragma unroll
    for (int i = 0; i < 2; i++)
        #pragma unroll
        for (int j = 0; j < 8; j++)
            #pragma unroll
            for (int q = 0; q < 4; q++) acc[i][j][q] = 0.f;

    for (int kt = 0; kt < KT; kt++) {
        asm volatile("cp.async.wait_group %0;" :: "n"(STAGES - 2));
        __syncthreads();

        int nstage = kt + STAGES - 1;
        if (nstage < KT) issue(nstage, nstage % STAGES);
        asm volatile("cp.async.commit_group;");

        const uint32_t* as = (const uint32_t*)(As + (kt % STAGES) * TILE_H);
        const uint32_t* bs = (const uint32_t*)(Bs + (kt % STAGES) * TILE_H);
        // uint32 row stride = T_STRIDE/2 = 20; banks (20r + t) % 32 all distinct

        #pragma unroll
        for (int ks = 0; ks < TKK / 16; ks++) {
            uint32_t af[2][4], bf[8][2];
            #pragma unroll
            for (int i = 0; i < 2; i++) {
                int mrow = wm + i * 16;
                af[i][0] = as[(mrow + g    ) * 20 + ks * 8 + t];
                af[i][1] = as[(mrow + g + 8) * 20 + ks * 8 + t];
                af[i][2] = as[(mrow + g    ) * 20 + ks * 8 + t + 4];
                af[i][3] = as[(mrow + g + 8) * 20 + ks * 8 + t + 4];
            }
            #pragma unroll
            for (int j = 0; j < 8; j++) {
                int nrow = wn + j * 8 + g;
                bf[j][0] = bs[nrow * 20 + ks * 8 + t];
                bf[j][1] = bs[nrow * 20 + ks * 8 + t + 4];
            }
            #pragma unroll
            for (int i = 0; i < 2; i++)
                #pragma unroll
                for (int j = 0; j < 8; j++)
                    mma_f16(acc[i][j], af[i], bf[j]);
        }
    }

    // epilogue
    const float* bb = Ball + (size_t)e * ND + n0;
    #pragma unroll
    for (int i = 0; i < 2; i++) {
        int r0 = wm + i * 16 + g;
        int r1 = r0 + 8;
        int a0 = rows[r0], a1 = rows[r1];
        #pragma unroll
        for (int j = 0; j < 8; j++) {
            int col = wn + j * 8 + t * 2;
            float bx = bb[col], by = bb[col + 1];
            if (UP) {
                if (a0 >= 0) {
                    float v0 = gelu_tanh(acc[i][j][0] + bx);
                    float v1 = gelu_tanh(acc[i][j][1] + by);
                    *(__half2*)(g_hh + (size_t)a0 * HID + n0 + col) = __floats2half2_rn(v0, v1);
                }
                if (a1 >= 0) {
                    float v2 = gelu_tanh(acc[i][j][2] + bx);
                    float v3 = gelu_tanh(acc[i][j][3] + by);
                    *(__half2*)(g_hh + (size_t)a1 * HID + n0 + col) = __floats2half2_rn(v2, v3);
                }
            } else {
                if (a0 >= 0)
                    *(float2*)(g_y + (size_t)a0 * DIM + n0 + col) =
                        make_float2(acc[i][j][0] + bx, acc[i][j][1] + by);
                if (a1 >= 0)
                    *(float2*)(g_y + (size_t)a1 * DIM + n0 + col) =
                        make_float2(acc[i][j][2] + bx, acc[i][j][3] + by);
            }
        }
    }
}

// ---------------- kernel: deterministic weighted combine ----------------
__global__ __launch_bounds__(256) void combine_kernel(float* __restrict__ out) {
    int t = blockIdx.x;
    float w0 = g_topk_w[t * TOPK + 0];
    float w1 = g_topk_w[t * TOPK + 1];
    const float4* y0 = (const float4*)(g_y + (size_t)(t * TOPK + 0) * DIM);
    const float4* y1 = (const float4*)(g_y + (size_t)(t * TOPK + 1) * DIM);
    float4* o = (float4*)(out + (size_t)t * DIM);
    for (int d = threadIdx.x; d < DIM / 4; d += 256) {
        float4 a = y0[d], b = y1[d];
        float4 r;
        r.x = w0 * a.x + w1 * b.x;
        r.y = w0 * a.y + w1 * b.y;
        r.z = w0 * a.z + w1 * b.z;
        r.w = w0 * a.w + w1 * b.w;
        o[d] = r;
    }
}

// ---------------- launch ----------------
extern "C" void kernel_launch(void* const* d_in, const int* in_sizes, int n_in,
                              void* d_out, int out_size)
{
    const float* x  = (const float*)d_in[0];
    const float* rw = (const float*)d_in[1];
    const float* rb = (const float*)d_in[2];
    const float* wu = (const float*)d_in[3];
    const float* bu = (const float*)d_in[4];
    const float* wd = (const float*)d_in[5];
    const float* bd = (const float*)d_in[6];

    float* out       = (float*)d_out;
    float* out_y     = out;
    float* out_aux   = out + (size_t)NTOK * DIM;
    float* out_probs = out_aux + 1;

    cudaFuncSetAttribute(mma_gemm_kernel<true>,
        cudaFuncAttributeMaxDynamicSharedMemorySize, SMEM_BYTES);
    cudaFuncSetAttribute(mma_gemm_kernel<false>,
        cudaFuncAttributeMaxDynamicSharedMemorySize, SMEM_BYTES);

    __half* d_wuh = nullptr; cudaGetSymbolAddress((void**)&d_wuh, g_wuh);
    __half* d_wdh = nullptr; cudaGetSymbolAddress((void**)&d_wdh, g_wdh);

    zero_kernel<<<1, 32>>>();
    router_kernel<<<NTOK, 256>>>(x, rw, rb, out_probs);
    aux_kernel<<<1, 32>>>(out_aux);

    cvt_x_kernel<<<1184, 256>>>((const float4*)x, NTOK * DIM / 4);
    dim3 tu(HID / 32, DIM / 32, NE);
    trans_cvt_kernel<DIM, HID><<<tu, 256>>>(wu, d_wuh);
    dim3 td(DIM / 32, HID / 32, NE);
    trans_cvt_kernel<HID, DIM><<<td, 256>>>(wd, d_wdh);

    dim3 gu(HID / TN, CAP / TM, NE);
    mma_gemm_kernel<true><<<gu, 256, SMEM_BYTES>>>(bu);

    dim3 gd(DIM / TN, CAP / TM, NE);
    mma_gemm_kernel<false><<<gd, 256, SMEM_BYTES>>>(bd);

    combine_kernel<<<NTOK, 256>>>(out_y);
}

// round 8
// speedup vs baseline: 1.4940x; 1.0589x over previous
#include <cuda_runtime.h>
#include <cuda_fp16.h>
#include <math.h>
#include <cstdint>

#define NTOK 8192      // B*S
#define DIM  1024      // d_model
#define NE   8         // experts
#define TOPK 2
#define HID  4096      // expert hidden
#define NA   (NTOK*TOPK)   // 16384 assignments
#define CAP  NA            // per-expert bucket capacity (worst case)

// ---------------- device scratch (no allocations allowed) ----------------
__device__ int    g_bucket[NE*CAP];
__device__ int    g_cursor[NE];
__device__ float  g_prob_sum[NE];
__device__ float  g_topk_w[NA];
__device__ float  g_y[(size_t)NA*DIM];            // 67 MB
__device__ __half g_xh[(size_t)NTOK*DIM];         // fp16 x, 16.8 MB
__device__ __half g_wuh[(size_t)NE*HID*DIM];      // fp16 w_up^T  [e][n][k], 67 MB
__device__ __half g_wdh[(size_t)NE*DIM*HID];      // fp16 w_down^T[e][n][k], 67 MB
__device__ __half g_hh[(size_t)NA*HID];           // fp16 activations, 134 MB

// ---------------- kernel: zero ----------------
__global__ void zero_kernel() {
    int t = threadIdx.x;
    if (t < NE) { g_cursor[t] = 0; g_prob_sum[t] = 0.f; }
}

// ---------------- kernel: router ----------------
__global__ __launch_bounds__(256) void router_kernel(
    const float* __restrict__ x, const float* __restrict__ rw,
    const float* __restrict__ rb, float* __restrict__ probs_out)
{
    int t   = blockIdx.x;
    int tid = threadIdx.x;
    const float* xr = x + (size_t)t * DIM;

    float acc[NE];
    #pragma unroll
    for (int e = 0; e < NE; e++) acc[e] = 0.f;

    for (int d = tid; d < DIM; d += 256) {
        float xv = xr[d];
        const float* w = rw + (size_t)d * NE;
        #pragma unroll
        for (int e = 0; e < NE; e++) acc[e] += xv * w[e];
    }
    #pragma unroll
    for (int e = 0; e < NE; e++) {
        #pragma unroll
        for (int off = 16; off > 0; off >>= 1)
            acc[e] += __shfl_down_sync(0xffffffffu, acc[e], off);
    }
    __shared__ float wsum[8][NE];
    int warp = tid >> 5, lane = tid & 31;
    if (lane == 0) {
        #pragma unroll
        for (int e = 0; e < NE; e++) wsum[warp][e] = acc[e];
    }
    __syncthreads();

    if (tid == 0) {
        float lg[NE];
        #pragma unroll
        for (int e = 0; e < NE; e++) {
            float s = rb[e];
            #pragma unroll
            for (int w = 0; w < 8; w++) s += wsum[w][e];
            lg[e] = s;
        }
        float mx = lg[0];
        #pragma unroll
        for (int e = 1; e < NE; e++) mx = fmaxf(mx, lg[e]);
        float p[NE], den = 0.f;
        #pragma unroll
        for (int e = 0; e < NE; e++) { p[e] = expf(lg[e] - mx); den += p[e]; }
        float inv = 1.f / den;
        #pragma unroll
        for (int e = 0; e < NE; e++) {
            p[e] *= inv;
            probs_out[(size_t)t * NE + e] = p[e];
            atomicAdd(&g_prob_sum[e], p[e]);
        }
        int i0 = 0;
        #pragma unroll
        for (int e = 1; e < NE; e++) if (lg[e] > lg[i0]) i0 = e;
        int i1 = -1;
        #pragma unroll
        for (int e = 0; e < NE; e++)
            if (e != i0 && (i1 < 0 || lg[e] > lg[i1])) i1 = e;
        float e1 = expf(lg[i1] - lg[i0]);
        float p0 = 1.f / (1.f + e1);
        float p1 = e1 * p0;

        int a0 = t * TOPK + 0, a1 = t * TOPK + 1;
        g_topk_w[a0] = p0;
        g_topk_w[a1] = p1;
        int s0 = atomicAdd(&g_cursor[i0], 1);
        g_bucket[i0 * CAP + s0] = a0;
        int s1 = atomicAdd(&g_cursor[i1], 1);
        g_bucket[i1 * CAP + s1] = a1;
    }
}

// ---------------- kernel: aux loss ----------------
__global__ void aux_kernel(float* __restrict__ out_aux) {
    if (threadIdx.x == 0) {
        float s = 0.f;
        #pragma unroll
        for (int e = 0; e < NE; e++)
            s += ((float)g_cursor[e] / (float)NA) * (g_prob_sum[e] / (float)NTOK);
        *out_aux = (float)NE * s * 0.01f;
    }
}

// ---------------- kernel: convert x to fp16 ----------------
__global__ __launch_bounds__(256) void cvt_x_kernel(const float4* __restrict__ src, int n4) {
    int stride = gridDim.x * blockDim.x;
    for (int i = blockIdx.x * blockDim.x + threadIdx.x; i < n4; i += stride) {
        float4 v = src[i];
        __half2 h01 = __floats2half2_rn(v.x, v.y);
        __half2 h23 = __floats2half2_rn(v.z, v.w);
        ((uint2*)g_xh)[i] = make_uint2(*(uint32_t*)&h01, *(uint32_t*)&h23);
    }
}

// ---------------- kernel: transpose + convert weights to fp16 ----------------
// W [E][KD][ND] fp32 -> Wt [E][ND][KD] fp16
template<int KD, int ND>
__global__ __launch_bounds__(256) void trans_cvt_kernel(
    const float* __restrict__ W, __half* __restrict__ Wt)
{
    __shared__ float tile[32][33];
    int e  = blockIdx.z;
    int n0 = blockIdx.x * 32;
    int k0 = blockIdx.y * 32;
    int tx = threadIdx.x & 31, ty = threadIdx.x >> 5;
    const float* src = W + (size_t)e * KD * ND;
    #pragma unroll
    for (int i = ty; i < 32; i += 8)
        tile[i][tx] = src[(size_t)(k0 + i) * ND + n0 + tx];
    __syncthreads();
    __half* dst = Wt + (size_t)e * ND * KD;
    #pragma unroll
    for (int i = ty; i < 32; i += 8)
        dst[(size_t)(n0 + i) * KD + k0 + tx] = __float2half(tile[tx][i]);
}

// ---------------- fp16 tensor-core grouped GEMM ----------------
// 256 threads, 8 warps (4x2 grid of 32x64 warp tiles), m16n8k16 fp16 mma,
// ldmatrix.x4 fragment loads (6 LDSM per ks-step vs 24 scalar LDS).
#define TM 128
#define TN 128
#define TKK 32
#define STAGES 3
#define T_STRIDE 40    // fp16 elems per row (80B); 8-row LDSM phase hits all 32 banks once
#define TILE_H (TM*T_STRIDE)
#define SMEM_BYTES (STAGES*TILE_H*2*2 + TM*4)

__device__ __forceinline__ float gelu_tanh(float v) {
    float c = v * v * v;
    return 0.5f * v * (1.f + tanhf(0.7978845608028654f * (v + 0.044715f * c)));
}

__device__ __forceinline__ void mma_f16(float* c, const uint32_t* a, const uint32_t* b) {
    asm volatile(
        "mma.sync.aligned.m16n8k16.row.col.f32.f16.f16.f32 "
        "{%0,%1,%2,%3}, {%4,%5,%6,%7}, {%8,%9}, {%0,%1,%2,%3};"
        : "+f"(c[0]), "+f"(c[1]), "+f"(c[2]), "+f"(c[3])
        : "r"(a[0]), "r"(a[1]), "r"(a[2]), "r"(a[3]), "r"(b[0]), "r"(b[1]));
}

__device__ __forceinline__ void ldsm_x4(uint32_t& r0, uint32_t& r1, uint32_t& r2, uint32_t& r3,
                                        uint32_t addr) {
    asm volatile("ldmatrix.sync.aligned.m8n8.x4.shared.b16 {%0,%1,%2,%3}, [%4];"
                 : "=r"(r0), "=r"(r1), "=r"(r2), "=r"(r3) : "r"(addr));
}

__device__ __forceinline__ void cp_async16(void* dst, const void* src, bool pred) {
    uint32_t d = (uint32_t)__cvta_generic_to_shared(dst);
    int sz = pred ? 16 : 0;
    asm volatile("cp.async.cg.shared.global [%0], [%1], 16, %2;\n"
                 :: "r"(d), "l"(src), "r"(sz));
}

// UP:  A = gathered g_xh rows, B = g_wuh[e] [HID][DIM], epilogue = gelu -> g_hh (fp16)
// DN:  A = gathered g_hh rows, B = g_wdh[e] [DIM][HID], epilogue = +bias -> g_y (fp32)
template<bool UP>
__global__ __launch_bounds__(256, 1)
void mma_gemm_kernel(const float* __restrict__ Ball)
{
    constexpr int KD = UP ? DIM : HID;
    constexpr int ND = UP ? HID : DIM;
    constexpr int KT = KD / TKK;

    int e   = blockIdx.z;
    int cnt = g_cursor[e];
    int m0  = blockIdx.y * TM;
    if (m0 >= cnt) return;
    int n0  = blockIdx.x * TN;

    extern __shared__ __half smem[];
    __half* As = smem;                         // [STAGES][TM][T_STRIDE]
    __half* Bs = smem + STAGES * TILE_H;       // [STAGES][TN][T_STRIDE]
    int*   rows = (int*)(smem + 2 * STAGES * TILE_H);

    int tid = threadIdx.x;
    if (tid < TM) {
        int m = m0 + tid;
        rows[tid] = (m < cnt) ? g_bucket[e * CAP + m] : -1;
    }
    __syncthreads();

    const __half* W = (UP ? g_wuh : g_wdh) + (size_t)e * (size_t)ND * KD;
    const __half* Abase = UP ? (const __half*)g_xh : (const __half*)g_hh;

    auto issue = [&](int kt, int stage) {
        __half* as = As + stage * TILE_H;
        __half* bs = Bs + stage * TILE_H;
        int kbase = kt * TKK;
        #pragma unroll
        for (int i = 0; i < 2; i++) {          // A: 128 rows x 4 chunks of 16B
            int c = tid + i * 256;
            int r = c >> 2, q = c & 3;
            int a = rows[r];
            bool pred = (a >= 0);
            const __half* src = Abase +
                (UP ? (size_t)(pred ? (a >> 1) : 0) * DIM
                    : (size_t)(pred ? a : 0) * HID) + kbase + q * 8;
            cp_async16(as + r * T_STRIDE + q * 8, src, pred);
        }
        #pragma unroll
        for (int i = 0; i < 2; i++) {          // B: 128 n-rows x 4 chunks
            int c = tid + i * 256;
            int r = c >> 2, q = c & 3;
            cp_async16(bs + r * T_STRIDE + q * 8,
                       W + (size_t)(n0 + r) * KD + kbase + q * 8, true);
        }
    };

    #pragma unroll
    for (int s = 0; s < STAGES - 1; s++) {
        if (s < KT) issue(s, s);
        asm volatile("cp.async.commit_group;");
    }

    int wid = tid >> 5, lane = tid & 31;
    int g = lane >> 2, t = lane & 3;
    int wm = (wid >> 1) * 32;   // 4x2 warp grid, 32x64 warp tiles
    int wn = (wid & 1) * 64;

    // ldmatrix per-lane row addressing (halves):
    int sub = lane >> 3, r8 = lane & 7;
    // A x4: m0 rows 0-7 k0 | m1 rows 8-15 k0 | m2 rows 0-7 k8 | m3 rows 8-15 k8
    int a_off = (wm + (sub & 1) * 8 + r8) * T_STRIDE + (sub >> 1) * 8;
    // B x4: m0 n(j)0-7 k0 | m1 n(j) k8 | m2 n(j+1) k0 | m3 n(j+1) k8
    int b_off = (wn + (sub >> 1) * 8 + r8) * T_STRIDE + (sub & 1) * 8;

    float acc[2][8][4];
    #pragma unroll
    for (int i = 0; i < 2; i++)
        #pragma unroll
        for (int j = 0; j < 8; j++)
            #pragma unroll
            for (int q = 0; q < 4; q++) acc[i][j][q] = 0.f;

    for (int kt = 0; kt < KT; kt++) {
        asm volatile("cp.async.wait_group %0;" :: "n"(STAGES - 2));
        __syncthreads();

        int nstage = kt + STAGES - 1;
        if (nstage < KT) issue(nstage, nstage % STAGES);
        asm volatile("cp.async.commit_group;");

        int st = kt % STAGES;
        uint32_t as_base = (uint32_t)__cvta_generic_to_shared(As + st * TILE_H) + a_off * 2;
        uint32_t bs_base = (uint32_t)__cvta_generic_to_shared(Bs + st * TILE_H) + b_off * 2;

        #pragma unroll
        for (int ks = 0; ks < TKK / 16; ks++) {
            uint32_t af[2][4], bf[8][2];
            #pragma unroll
            for (int i = 0; i < 2; i++)
                ldsm_x4(af[i][0], af[i][1], af[i][2], af[i][3],
                        as_base + (i * 16 * T_STRIDE + ks * 16) * 2);
            #pragma unroll
            for (int jp = 0; jp < 4; jp++)
                ldsm_x4(bf[2*jp][0], bf[2*jp][1], bf[2*jp+1][0], bf[2*jp+1][1],
                        bs_base + (jp * 16 * T_STRIDE + ks * 16) * 2);
            #pragma unroll
            for (int i = 0; i < 2; i++)
                #pragma unroll
                for (int j = 0; j < 8; j++)
                    mma_f16(acc[i][j], af[i], bf[j]);
        }
    }

    // epilogue
    const float* bb = Ball + (size_t)e * ND + n0;
    #pragma unroll
    for (int i = 0; i < 2; i++) {
        int r0 = wm + i * 16 + g;
        int r1 = r0 + 8;
        int a0 = rows[r0], a1 = rows[r1];
        #pragma unroll
        for (int j = 0; j < 8; j++) {
            int col = wn + j * 8 + t * 2;
            float bx = bb[col], by = bb[col + 1];
            if (UP) {
                if (a0 >= 0) {
                    float v0 = gelu_tanh(acc[i][j][0] + bx);
                    float v1 = gelu_tanh(acc[i][j][1] + by);
                    *(__half2*)(g_hh + (size_t)a0 * HID + n0 + col) = __floats2half2_rn(v0, v1);
                }
                if (a1 >= 0) {
                    float v2 = gelu_tanh(acc[i][j][2] + bx);
                    float v3 = gelu_tanh(acc[i][j][3] + by);
                    *(__half2*)(g_hh + (size_t)a1 * HID + n0 + col) = __floats2half2_rn(v2, v3);
                }
            } else {
                if (a0 >= 0)
                    *(float2*)(g_y + (size_t)a0 * DIM + n0 + col) =
                        make_float2(acc[i][j][0] + bx, acc[i][j][1] + by);
                if (a1 >= 0)
                    *(float2*)(g_y + (size_t)a1 * DIM + n0 + col) =
                        make_float2(acc[i][j][2] + bx, acc[i][j][3] + by);
            }
        }
    }
}

// ---------------- kernel: deterministic weighted combine ----------------
__global__ __launch_bounds__(256) void combine_kernel(float* __restrict__ out) {
    int t = blockIdx.x;
    float w0 = g_topk_w[t * TOPK + 0];
    float w1 = g_topk_w[t * TOPK + 1];
    const float4* y0 = (const float4*)(g_y + (size_t)(t * TOPK + 0) * DIM);
    const float4* y1 = (const float4*)(g_y + (size_t)(t * TOPK + 1) * DIM);
    float4* o = (float4*)(out + (size_t)t * DIM);
    for (int d = threadIdx.x; d < DIM / 4; d += 256) {
        float4 a = y0[d], b = y1[d];
        float4 r;
        r.x = w0 * a.x + w1 * b.x;
        r.y = w0 * a.y + w1 * b.y;
        r.z = w0 * a.z + w1 * b.z;
        r.w = w0 * a.w + w1 * b.w;
        o[d] = r;
    }
}

// ---------------- launch ----------------
extern "C" void kernel_launch(void* const* d_in, const int* in_sizes, int n_in,
                              void* d_out, int out_size)
{
    const float* x  = (const float*)d_in[0];
    const float* rw = (const float*)d_in[1];
    const float* rb = (const float*)d_in[2];
    const float* wu = (const float*)d_in[3];
    const float* bu = (const float*)d_in[4];
    const float* wd = (const float*)d_in[5];
    const float* bd = (const float*)d_in[6];

    float* out       = (float*)d_out;
    float* out_y     = out;
    float* out_aux   = out + (size_t)NTOK * DIM;
    float* out_probs = out_aux + 1;

    cudaFuncSetAttribute(mma_gemm_kernel<true>,
        cudaFuncAttributeMaxDynamicSharedMemorySize, SMEM_BYTES);
    cudaFuncSetAttribute(mma_gemm_kernel<false>,
        cudaFuncAttributeMaxDynamicSharedMemorySize, SMEM_BYTES);

    __half* d_wuh = nullptr; cudaGetSymbolAddress((void**)&d_wuh, g_wuh);
    __half* d_wdh = nullptr; cudaGetSymbolAddress((void**)&d_wdh, g_wdh);

    zero_kernel<<<1, 32>>>();
    router_kernel<<<NTOK, 256>>>(x, rw, rb, out_probs);
    aux_kernel<<<1, 32>>>(out_aux);

    cvt_x_kernel<<<1184, 256>>>((const float4*)x, NTOK * DIM / 4);
    dim3 tu(HID / 32, DIM / 32, NE);
    trans_cvt_kernel<DIM, HID><<<tu, 256>>>(wu, d_wuh);
    dim3 td(DIM / 32, HID / 32, NE);
    trans_cvt_kernel<HID, DIM><<<td, 256>>>(wd, d_wdh);

    dim3 gu(HID / TN, CAP / TM, NE);
    mma_gemm_kernel<true><<<gu, 256, SMEM_BYTES>>>(bu);

    dim3 gd(DIM / TN, CAP / TM, NE);
    mma_gemm_kernel<false><<<gd, 256, SMEM_BYTES>>>(bd);

    combine_kernel<<<NTOK, 256>>>(out_y);
}

// round 9
// speedup vs baseline: 2.1143x; 1.4152x over previous
#include <cuda_runtime.h>
#include <cuda_fp16.h>
#include <math.h>
#include <cstdint>

#define NTOK 8192      // B*S
#define DIM  1024      // d_model
#define NE   8         // experts
#define TOPK 2
#define HID  4096      // expert hidden
#define NA   (NTOK*TOPK)   // 16384 assignments
#define CAP  NA            // per-expert bucket capacity (worst case)

// ---------------- device scratch (no allocations allowed) ----------------
__device__ int    g_bucket[NE*CAP];
__device__ int    g_cursor[NE];
__device__ float  g_prob_sum[NE];
__device__ float  g_topk_w[NA];
__device__ float  g_y[(size_t)NA*DIM];            // 67 MB
__device__ __half g_xh[(size_t)NTOK*DIM];         // fp16 x, 16.8 MB
__device__ __half g_wuh[(size_t)NE*HID*DIM];      // fp16 w_up^T  [e][n][k], 67 MB
__device__ __half g_wdh[(size_t)NE*DIM*HID];      // fp16 w_down^T[e][n][k], 67 MB
__device__ __half g_hh[(size_t)NA*HID];           // fp16 activations, 134 MB

// ---------------- kernel 1: convert x to fp16 (+ zero accumulators) -------
__global__ __launch_bounds__(256) void cvt_x_kernel(const float4* __restrict__ src, int n4) {
    if (blockIdx.x == 0 && threadIdx.x < NE) {
        g_cursor[threadIdx.x] = 0;
        g_prob_sum[threadIdx.x] = 0.f;
    }
    int stride = gridDim.x * blockDim.x;
    for (int i = blockIdx.x * blockDim.x + threadIdx.x; i < n4; i += stride) {
        float4 v = src[i];
        __half2 h01 = __floats2half2_rn(v.x, v.y);
        __half2 h23 = __floats2half2_rn(v.z, v.w);
        ((uint2*)g_xh)[i] = make_uint2(*(uint32_t*)&h01, *(uint32_t*)&h23);
    }
}

// ---------------- kernel 2: fused transpose+convert of both weights -------
// W [E][KD][ND] fp32 -> Wt [E][ND][KD] fp16. Flat grid: first 32768 tiles are
// w_up, next 32768 are w_down (each expert has (KD/32)*(ND/32)=4096 tiles).
__global__ __launch_bounds__(256) void trans_cvt_fused_kernel(
    const float* __restrict__ wu, const float* __restrict__ wd,
    __half* __restrict__ wuh, __half* __restrict__ wdh)
{
    __shared__ float tile[32][33];
    int bid = blockIdx.x;
    bool up = bid < 32768;
    int b  = up ? bid : bid - 32768;
    int e  = b >> 12;          // /4096 tiles per expert
    int r  = b & 4095;
    int KD = up ? DIM : HID;
    int ND = up ? HID : DIM;
    int xT = ND >> 5;
    int n0 = (r % xT) << 5;
    int k0 = (r / xT) << 5;
    const float* src = (up ? wu : wd) + (size_t)e * KD * ND;
    __half* dst      = (up ? wuh : wdh) + (size_t)e * ND * KD;
    int tx = threadIdx.x & 31, ty = threadIdx.x >> 5;
    #pragma unroll
    for (int i = ty; i < 32; i += 8)
        tile[i][tx] = src[(size_t)(k0 + i) * ND + n0 + tx];
    __syncthreads();
    #pragma unroll
    for (int i = ty; i < 32; i += 8)
        dst[(size_t)(n0 + i) * KD + k0 + tx] = __float2half(tile[tx][i]);
}

// ---------------- kernel 3: router ----------------
__global__ __launch_bounds__(256) void router_kernel(
    const float* __restrict__ x, const float* __restrict__ rw,
    const float* __restrict__ rb, float* __restrict__ probs_out)
{
    int t   = blockIdx.x;
    int tid = threadIdx.x;
    const float* xr = x + (size_t)t * DIM;

    float acc[NE];
    #pragma unroll
    for (int e = 0; e < NE; e++) acc[e] = 0.f;

    for (int d = tid; d < DIM; d += 256) {
        float xv = xr[d];
        const float* w = rw + (size_t)d * NE;
        #pragma unroll
        for (int e = 0; e < NE; e++) acc[e] += xv * w[e];
    }
    #pragma unroll
    for (int e = 0; e < NE; e++) {
        #pragma unroll
        for (int off = 16; off > 0; off >>= 1)
            acc[e] += __shfl_down_sync(0xffffffffu, acc[e], off);
    }
    __shared__ float wsum[8][NE];
    int warp = tid >> 5, lane = tid & 31;
    if (lane == 0) {
        #pragma unroll
        for (int e = 0; e < NE; e++) wsum[warp][e] = acc[e];
    }
    __syncthreads();

    if (tid == 0) {
        float lg[NE];
        #pragma unroll
        for (int e = 0; e < NE; e++) {
            float s = rb[e];
            #pragma unroll
            for (int w = 0; w < 8; w++) s += wsum[w][e];
            lg[e] = s;
        }
        float mx = lg[0];
        #pragma unroll
        for (int e = 1; e < NE; e++) mx = fmaxf(mx, lg[e]);
        float p[NE], den = 0.f;
        #pragma unroll
        for (int e = 0; e < NE; e++) { p[e] = expf(lg[e] - mx); den += p[e]; }
        float inv = 1.f / den;
        #pragma unroll
        for (int e = 0; e < NE; e++) {
            p[e] *= inv;
            probs_out[(size_t)t * NE + e] = p[e];
            atomicAdd(&g_prob_sum[e], p[e]);
        }
        int i0 = 0;
        #pragma unroll
        for (int e = 1; e < NE; e++) if (lg[e] > lg[i0]) i0 = e;
        int i1 = -1;
        #pragma unroll
        for (int e = 0; e < NE; e++)
            if (e != i0 && (i1 < 0 || lg[e] > lg[i1])) i1 = e;
        float e1 = expf(lg[i1] - lg[i0]);
        float p0 = 1.f / (1.f + e1);
        float p1 = e1 * p0;

        int a0 = t * TOPK + 0, a1 = t * TOPK + 1;
        g_topk_w[a0] = p0;
        g_topk_w[a1] = p1;
        int s0 = atomicAdd(&g_cursor[i0], 1);
        g_bucket[i0 * CAP + s0] = a0;
        int s1 = atomicAdd(&g_cursor[i1], 1);
        g_bucket[i1 * CAP + s1] = a1;
    }
}

// ---------------- kernel: aux loss ----------------
__global__ void aux_kernel(float* __restrict__ out_aux) {
    if (threadIdx.x == 0) {
        float s = 0.f;
        #pragma unroll
        for (int e = 0; e < NE; e++)
            s += ((float)g_cursor[e] / (float)NA) * (g_prob_sum[e] / (float)NTOK);
        *out_aux = (float)NE * s * 0.01f;
    }
}

// ---------------- fp16 tensor-core grouped GEMM ----------------
// 256 threads, 8 warps (4x2 grid of 32x64 warp tiles), m16n8k16 fp16 mma,
// ldmatrix.x4 fragment loads, TKK=64 slabs (half the barriers of TKK=32,
// 2-slab prefetch distance), 3-stage cp.async, 2 CTAs/SM.
#define TM 128
#define TN 128
#define TKK 64
#define STAGES 3
#define T_STRIDE 72    // fp16/row (144B); LDSM 8-row phase hits all 32 banks once
#define TILE_H (TM*T_STRIDE)
#define SMEM_BYTES (STAGES*TILE_H*2*2 + TM*4)

__device__ __forceinline__ float gelu_tanh(float v) {
    float c = v * v * v;
    return 0.5f * v * (1.f + tanhf(0.7978845608028654f * (v + 0.044715f * c)));
}

__device__ __forceinline__ void mma_f16(float* c, const uint32_t* a, const uint32_t* b) {
    asm volatile(
        "mma.sync.aligned.m16n8k16.row.col.f32.f16.f16.f32 "
        "{%0,%1,%2,%3}, {%4,%5,%6,%7}, {%8,%9}, {%0,%1,%2,%3};"
        : "+f"(c[0]), "+f"(c[1]), "+f"(c[2]), "+f"(c[3])
        : "r"(a[0]), "r"(a[1]), "r"(a[2]), "r"(a[3]), "r"(b[0]), "r"(b[1]));
}

__device__ __forceinline__ void ldsm_x4(uint32_t& r0, uint32_t& r1, uint32_t& r2, uint32_t& r3,
                                        uint32_t addr) {
    asm volatile("ldmatrix.sync.aligned.m8n8.x4.shared.b16 {%0,%1,%2,%3}, [%4];"
                 : "=r"(r0), "=r"(r1), "=r"(r2), "=r"(r3) : "r"(addr));
}

__device__ __forceinline__ void cp_async16(void* dst, const void* src, bool pred) {
    uint32_t d = (uint32_t)__cvta_generic_to_shared(dst);
    int sz = pred ? 16 : 0;
    asm volatile("cp.async.cg.shared.global [%0], [%1], 16, %2;\n"
                 :: "r"(d), "l"(src), "r"(sz));
}

// UP:  A = gathered g_xh rows, B = g_wuh[e] [HID][DIM], epilogue = gelu -> g_hh (fp16)
// DN:  A = gathered g_hh rows, B = g_wdh[e] [DIM][HID], epilogue = +bias -> g_y (fp32)
template<bool UP>
__global__ __launch_bounds__(256)
void mma_gemm_kernel(const float* __restrict__ Ball)
{
    constexpr int KD = UP ? DIM : HID;
    constexpr int ND = UP ? HID : DIM;
    constexpr int KT = KD / TKK;

    int e   = blockIdx.z;
    int cnt = g_cursor[e];
    int m0  = blockIdx.y * TM;
    if (m0 >= cnt) return;
    int n0  = blockIdx.x * TN;

    extern __shared__ __half smem[];
    __half* As = smem;                         // [STAGES][TM][T_STRIDE]
    __half* Bs = smem + STAGES * TILE_H;       // [STAGES][TN][T_STRIDE]
    int*   rows = (int*)(smem + 2 * STAGES * TILE_H);

    int tid = threadIdx.x;
    if (tid < TM) {
        int m = m0 + tid;
        rows[tid] = (m < cnt) ? g_bucket[e * CAP + m] : -1;
    }
    __syncthreads();

    const __half* W = (UP ? g_wuh : g_wdh) + (size_t)e * (size_t)ND * KD;
    const __half* Abase = UP ? (const __half*)g_xh : (const __half*)g_hh;

    auto issue = [&](int kt, int stage) {
        __half* as = As + stage * TILE_H;
        __half* bs = Bs + stage * TILE_H;
        int kbase = kt * TKK;
        #pragma unroll
        for (int i = 0; i < 4; i++) {          // A: 128 rows x 8 chunks of 16B
            int c = tid + i * 256;
            int r = c >> 3, q = c & 7;
            int a = rows[r];
            bool pred = (a >= 0);
            const __half* src = Abase +
                (UP ? (size_t)(pred ? (a >> 1) : 0) * DIM
                    : (size_t)(pred ? a : 0) * HID) + kbase + q * 8;
            cp_async16(as + r * T_STRIDE + q * 8, src, pred);
        }
        #pragma unroll
        for (int i = 0; i < 4; i++) {          // B: 128 n-rows x 8 chunks
            int c = tid + i * 256;
            int r = c >> 3, q = c & 7;
            cp_async16(bs + r * T_STRIDE + q * 8,
                       W + (size_t)(n0 + r) * KD + kbase + q * 8, true);
        }
    };

    #pragma unroll
    for (int s = 0; s < STAGES - 1; s++) {
        if (s < KT) issue(s, s);
        asm volatile("cp.async.commit_group;");
    }

    int wid = tid >> 5, lane = tid & 31;
    int g = lane >> 2, t = lane & 3;
    int wm = (wid >> 1) * 32;   // 4x2 warp grid, 32x64 warp tiles
    int wn = (wid & 1) * 64;

    // ldmatrix per-lane row addressing:
    int sub = lane >> 3, r8 = lane & 7;
    int a_off = (wm + (sub & 1) * 8 + r8) * T_STRIDE + (sub >> 1) * 8;
    int b_off = (wn + (sub >> 1) * 8 + r8) * T_STRIDE + (sub & 1) * 8;

    float acc[2][8][4];
    #pragma unroll
    for (int i = 0; i < 2; i++)
        #pragma unroll
        for (int j = 0; j < 8; j++)
            #pragma unroll
            for (int q = 0; q < 4; q++) acc[i][j][q] = 0.f;

    for (int kt = 0; kt < KT; kt++) {
        asm volatile("cp.async.wait_group %0;" :: "n"(STAGES - 2));
        __syncthreads();

        int nstage = kt + STAGES - 1;
        if (nstage < KT) issue(nstage, nstage % STAGES);
        asm volatile("cp.async.commit_group;");

        int st = kt % STAGES;
        uint32_t as_base = (uint32_t)__cvta_generic_to_shared(As + st * TILE_H) + a_off * 2;
        uint32_t bs_base = (uint32_t)__cvta_generic_to_shared(Bs + st * TILE_H) + b_off * 2;

        #pragma unroll
        for (int ks = 0; ks < TKK / 16; ks++) {
            uint32_t af[2][4], bf[8][2];
            #pragma unroll
            for (int i = 0; i < 2; i++)
                ldsm_x4(af[i][0], af[i][1], af[i][2], af[i][3],
                        as_base + (i * 16 * T_STRIDE + ks * 16) * 2);
            #pragma unroll
            for (int jp = 0; jp < 4; jp++)
                ldsm_x4(bf[2*jp][0], bf[2*jp][1], bf[2*jp+1][0], bf[2*jp+1][1],
                        bs_base + (jp * 16 * T_STRIDE + ks * 16) * 2);
            #pragma unroll
            for (int i = 0; i < 2; i++)
                #pragma unroll
                for (int j = 0; j < 8; j++)
                    mma_f16(acc[i][j], af[i], bf[j]);
        }
    }

    // epilogue
    const float* bb = Ball + (size_t)e * ND + n0;
    #pragma unroll
    for (int i = 0; i < 2; i++) {
        int r0 = wm + i * 16 + g;
        int r1 = r0 + 8;
        int a0 = rows[r0], a1 = rows[r1];
        #pragma unroll
        for (int j = 0; j < 8; j++) {
            int col = wn + j * 8 + t * 2;
            float bx = bb[col], by = bb[col + 1];
            if (UP) {
                if (a0 >= 0) {
                    float v0 = gelu_tanh(acc[i][j][0] + bx);
                    float v1 = gelu_tanh(acc[i][j][1] + by);
                    *(__half2*)(g_hh + (size_t)a0 * HID + n0 + col) = __floats2half2_rn(v0, v1);
                }
                if (a1 >= 0) {
                    float v2 = gelu_tanh(acc[i][j][2] + bx);
                    float v3 = gelu_tanh(acc[i][j][3] + by);
                    *(__half2*)(g_hh + (size_t)a1 * HID + n0 + col) = __floats2half2_rn(v2, v3);
                }
            } else {
                if (a0 >= 0)
                    *(float2*)(g_y + (size_t)a0 * DIM + n0 + col) =
                        make_float2(acc[i][j][0] + bx, acc[i][j][1] + by);
                if (a1 >= 0)
                    *(float2*)(g_y + (size_t)a1 * DIM + n0 + col) =
                        make_float2(acc[i][j][2] + bx, acc[i][j][3] + by);
            }
        }
    }
}

// ---------------- kernel: deterministic weighted combine ----------------
__global__ __launch_bounds__(256) void combine_kernel(float* __restrict__ out) {
    int t = blockIdx.x;
    float w0 = g_topk_w[t * TOPK + 0];
    float w1 = g_topk_w[t * TOPK + 1];
    const float4* y0 = (const float4*)(g_y + (size_t)(t * TOPK + 0) * DIM);
    const float4* y1 = (const float4*)(g_y + (size_t)(t * TOPK + 1) * DIM);
    float4* o = (float4*)(out + (size_t)t * DIM);
    for (int d = threadIdx.x; d < DIM / 4; d += 256) {
        float4 a = y0[d], b = y1[d];
        float4 r;
        r.x = w0 * a.x + w1 * b.x;
        r.y = w0 * a.y + w1 * b.y;
        r.z = w0 * a.z + w1 * b.z;
        r.w = w0 * a.w + w1 * b.w;
        o[d] = r;
    }
}

// ---------------- launch ----------------
extern "C" void kernel_launch(void* const* d_in, const int* in_sizes, int n_in,
                              void* d_out, int out_size)
{
    const float* x  = (const float*)d_in[0];
    const float* rw = (const float*)d_in[1];
    const float* rb = (const float*)d_in[2];
    const float* wu = (const float*)d_in[3];
    const float* bu = (const float*)d_in[4];
    const float* wd = (const float*)d_in[5];
    const float* bd = (const float*)d_in[6];

    float* out       = (float*)d_out;
    float* out_y     = out;
    float* out_aux   = out + (size_t)NTOK * DIM;
    float* out_probs = out_aux + 1;

    cudaFuncSetAttribute(mma_gemm_kernel<true>,
        cudaFuncAttributeMaxDynamicSharedMemorySize, SMEM_BYTES);
    cudaFuncSetAttribute(mma_gemm_kernel<false>,
        cudaFuncAttributeMaxDynamicSharedMemorySize, SMEM_BYTES);

    __half* d_wuh = nullptr; cudaGetSymbolAddress((void**)&d_wuh, g_wuh);
    __half* d_wdh = nullptr; cudaGetSymbolAddress((void**)&d_wdh, g_wdh);

    // launch order chosen so the up-GEMM is the 4th launch (ncu captures #4)
    cvt_x_kernel<<<1184, 256>>>((const float4*)x, NTOK * DIM / 4);       // 1 (+zero)
    trans_cvt_fused_kernel<<<65536, 256>>>(wu, wd, d_wuh, d_wdh);        // 2
    router_kernel<<<NTOK, 256>>>(x, rw, rb, out_probs);                  // 3

    dim3 gu(HID / TN, CAP / TM, NE);
    mma_gemm_kernel<true><<<gu, 256, SMEM_BYTES>>>(bu);                  // 4 <- profiled

    aux_kernel<<<1, 32>>>(out_aux);                                      // 5

    dim3 gd(DIM / TN, CAP / TM, NE);
    mma_gemm_kernel<false><<<gd, 256, SMEM_BYTES>>>(bd);                 // 6

    combine_kernel<<<NTOK, 256>>>(out_y);                                // 7
}

// round 10
// speedup vs baseline: 2.1265x; 1.0058x over previous
#include <cuda_runtime.h>
#include <cuda_fp16.h>
#include <math.h>
#include <cstdint>

#define NTOK 8192      // B*S
#define DIM  1024      // d_model
#define NE   8         // experts
#define TOPK 2
#define HID  4096      // expert hidden
#define NA   (NTOK*TOPK)   // 16384 assignments
#define CAP  NA            // per-expert bucket capacity (worst case)

// ---------------- device scratch (no allocations allowed) ----------------
__device__ int    g_bucket[NE*CAP];
__device__ int    g_cursor[NE];
__device__ float  g_prob_sum[NE];
__device__ float  g_topk_w[NA];
__device__ float  g_y[(size_t)NA*DIM];            // 67 MB
__device__ __half g_xh[(size_t)NTOK*DIM];         // fp16 x, 16.8 MB
__device__ __half g_wuh[(size_t)NE*HID*DIM];      // fp16 w_up^T  [e][n][k], 67 MB
__device__ __half g_wdh[(size_t)NE*DIM*HID];      // fp16 w_down^T[e][n][k], 67 MB
__device__ __half g_hh[(size_t)NA*HID];           // fp16 activations, 134 MB

// ---------------- kernel 1: convert x to fp16 (+ zero accumulators) -------
__global__ __launch_bounds__(256) void cvt_x_kernel(const float4* __restrict__ src, int n4) {
    if (blockIdx.x == 0 && threadIdx.x < NE) {
        g_cursor[threadIdx.x] = 0;
        g_prob_sum[threadIdx.x] = 0.f;
    }
    int stride = gridDim.x * blockDim.x;
    for (int i = blockIdx.x * blockDim.x + threadIdx.x; i < n4; i += stride) {
        float4 v = src[i];
        __half2 h01 = __floats2half2_rn(v.x, v.y);
        __half2 h23 = __floats2half2_rn(v.z, v.w);
        ((uint2*)g_xh)[i] = make_uint2(*(uint32_t*)&h01, *(uint32_t*)&h23);
    }
}

// ---------------- kernel 2: fused transpose+convert of both weights -------
__global__ __launch_bounds__(256) void trans_cvt_fused_kernel(
    const float* __restrict__ wu, const float* __restrict__ wd,
    __half* __restrict__ wuh, __half* __restrict__ wdh)
{
    __shared__ float tile[32][33];
    int bid = blockIdx.x;
    bool up = bid < 32768;
    int b  = up ? bid : bid - 32768;
    int e  = b >> 12;          // /4096 tiles per expert
    int r  = b & 4095;
    int KD = up ? DIM : HID;
    int ND = up ? HID : DIM;
    int xT = ND >> 5;
    int n0 = (r % xT) << 5;
    int k0 = (r / xT) << 5;
    const float* src = (up ? wu : wd) + (size_t)e * KD * ND;
    __half* dst      = (up ? wuh : wdh) + (size_t)e * ND * KD;
    int tx = threadIdx.x & 31, ty = threadIdx.x >> 5;
    #pragma unroll
    for (int i = ty; i < 32; i += 8)
        tile[i][tx] = src[(size_t)(k0 + i) * ND + n0 + tx];
    __syncthreads();
    #pragma unroll
    for (int i = ty; i < 32; i += 8)
        dst[(size_t)(n0 + i) * KD + k0 + tx] = __float2half(tile[tx][i]);
}

// ---------------- kernel 3: router ----------------
__global__ __launch_bounds__(256) void router_kernel(
    const float* __restrict__ x, const float* __restrict__ rw,
    const float* __restrict__ rb, float* __restrict__ probs_out)
{
    int t   = blockIdx.x;
    int tid = threadIdx.x;
    const float* xr = x + (size_t)t * DIM;

    float acc[NE];
    #pragma unroll
    for (int e = 0; e < NE; e++) acc[e] = 0.f;

    for (int d = tid; d < DIM; d += 256) {
        float xv = xr[d];
        const float* w = rw + (size_t)d * NE;
        #pragma unroll
        for (int e = 0; e < NE; e++) acc[e] += xv * w[e];
    }
    #pragma unroll
    for (int e = 0; e < NE; e++) {
        #pragma unroll
        for (int off = 16; off > 0; off >>= 1)
            acc[e] += __shfl_down_sync(0xffffffffu, acc[e], off);
    }
    __shared__ float wsum[8][NE];
    int warp = tid >> 5, lane = tid & 31;
    if (lane == 0) {
        #pragma unroll
        for (int e = 0; e < NE; e++) wsum[warp][e] = acc[e];
    }
    __syncthreads();

    if (tid == 0) {
        float lg[NE];
        #pragma unroll
        for (int e = 0; e < NE; e++) {
            float s = rb[e];
            #pragma unroll
            for (int w = 0; w < 8; w++) s += wsum[w][e];
            lg[e] = s;
        }
        float mx = lg[0];
        #pragma unroll
        for (int e = 1; e < NE; e++) mx = fmaxf(mx, lg[e]);
        float p[NE], den = 0.f;
        #pragma unroll
        for (int e = 0; e < NE; e++) { p[e] = expf(lg[e] - mx); den += p[e]; }
        float inv = 1.f / den;
        #pragma unroll
        for (int e = 0; e < NE; e++) {
            p[e] *= inv;
            probs_out[(size_t)t * NE + e] = p[e];
            atomicAdd(&g_prob_sum[e], p[e]);
        }
        int i0 = 0;
        #pragma unroll
        for (int e = 1; e < NE; e++) if (lg[e] > lg[i0]) i0 = e;
        int i1 = -1;
        #pragma unroll
        for (int e = 0; e < NE; e++)
            if (e != i0 && (i1 < 0 || lg[e] > lg[i1])) i1 = e;
        float e1 = expf(lg[i1] - lg[i0]);
        float p0 = 1.f / (1.f + e1);
        float p1 = e1 * p0;

        int a0 = t * TOPK + 0, a1 = t * TOPK + 1;
        g_topk_w[a0] = p0;
        g_topk_w[a1] = p1;
        int s0 = atomicAdd(&g_cursor[i0], 1);
        g_bucket[i0 * CAP + s0] = a0;
        int s1 = atomicAdd(&g_cursor[i1], 1);
        g_bucket[i1 * CAP + s1] = a1;
    }
}

// ---------------- kernel: aux loss ----------------
__global__ void aux_kernel(float* __restrict__ out_aux) {
    if (threadIdx.x == 0) {
        float s = 0.f;
        #pragma unroll
        for (int e = 0; e < NE; e++)
            s += ((float)g_cursor[e] / (float)NA) * (g_prob_sum[e] / (float)NTOK);
        *out_aux = (float)NE * s * 0.01f;
    }
}

// ---------------- fp16 tensor-core grouped GEMM ----------------
// 256 threads, 8 warps (4x2 grid of 32x64 warp tiles), m16n8k16 fp16 mma,
// ldmatrix.x4 fragment loads, TKK=64 slabs, 3-stage cp.async, 2 CTAs/SM,
// ks-level register double-buffered fragments (LDSM(ks+1) overlaps mma(ks)).
#define TM 128
#define TN 128
#define TKK 64
#define STAGES 3
#define T_STRIDE 72    // fp16/row (144B); LDSM 8-row phase hits all 32 banks once
#define TILE_H (TM*T_STRIDE)
#define SMEM_BYTES (STAGES*TILE_H*2*2 + TM*4)

__device__ __forceinline__ float gelu_tanh(float v) {
    float c = v * v * v;
    return 0.5f * v * (1.f + tanhf(0.7978845608028654f * (v + 0.044715f * c)));
}

__device__ __forceinline__ void mma_f16(float* c, const uint32_t* a, const uint32_t* b) {
    asm volatile(
        "mma.sync.aligned.m16n8k16.row.col.f32.f16.f16.f32 "
        "{%0,%1,%2,%3}, {%4,%5,%6,%7}, {%8,%9}, {%0,%1,%2,%3};"
        : "+f"(c[0]), "+f"(c[1]), "+f"(c[2]), "+f"(c[3])
        : "r"(a[0]), "r"(a[1]), "r"(a[2]), "r"(a[3]), "r"(b[0]), "r"(b[1]));
}

__device__ __forceinline__ void ldsm_x4(uint32_t& r0, uint32_t& r1, uint32_t& r2, uint32_t& r3,
                                        uint32_t addr) {
    asm volatile("ldmatrix.sync.aligned.m8n8.x4.shared.b16 {%0,%1,%2,%3}, [%4];"
                 : "=r"(r0), "=r"(r1), "=r"(r2), "=r"(r3) : "r"(addr));
}

__device__ __forceinline__ void cp_async16(void* dst, const void* src, bool pred) {
    uint32_t d = (uint32_t)__cvta_generic_to_shared(dst);
    int sz = pred ? 16 : 0;
    asm volatile("cp.async.cg.shared.global [%0], [%1], 16, %2;\n"
                 :: "r"(d), "l"(src), "r"(sz));
}

// UP:  A = gathered g_xh rows, B = g_wuh[e] [HID][DIM], epilogue = gelu -> g_hh (fp16)
// DN:  A = gathered g_hh rows, B = g_wdh[e] [DIM][HID], epilogue = +bias -> g_y (fp32)
template<bool UP>
__global__ __launch_bounds__(256, 2)
void mma_gemm_kernel(const float* __restrict__ Ball)
{
    constexpr int KD = UP ? DIM : HID;
    constexpr int ND = UP ? HID : DIM;
    constexpr int KT = KD / TKK;

    int e   = blockIdx.z;
    int cnt = g_cursor[e];
    int m0  = blockIdx.y * TM;
    if (m0 >= cnt) return;
    int n0  = blockIdx.x * TN;

    extern __shared__ __half smem[];
    __half* As = smem;                         // [STAGES][TM][T_STRIDE]
    __half* Bs = smem + STAGES * TILE_H;       // [STAGES][TN][T_STRIDE]
    int*   rows = (int*)(smem + 2 * STAGES * TILE_H);

    int tid = threadIdx.x;
    if (tid < TM) {
        int m = m0 + tid;
        rows[tid] = (m < cnt) ? g_bucket[e * CAP + m] : -1;
    }
    __syncthreads();

    const __half* W = (UP ? g_wuh : g_wdh) + (size_t)e * (size_t)ND * KD;
    const __half* Abase = UP ? (const __half*)g_xh : (const __half*)g_hh;

    auto issue = [&](int kt, int stage) {
        __half* as = As + stage * TILE_H;
        __half* bs = Bs + stage * TILE_H;
        int kbase = kt * TKK;
        #pragma unroll
        for (int i = 0; i < 4; i++) {          // A: 128 rows x 8 chunks of 16B
            int c = tid + i * 256;
            int r = c >> 3, q = c & 7;
            int a = rows[r];
            bool pred = (a >= 0);
            const __half* src = Abase +
                (UP ? (size_t)(pred ? (a >> 1) : 0) * DIM
                    : (size_t)(pred ? a : 0) * HID) + kbase + q * 8;
            cp_async16(as + r * T_STRIDE + q * 8, src, pred);
        }
        #pragma unroll
        for (int i = 0; i < 4; i++) {          // B: 128 n-rows x 8 chunks
            int c = tid + i * 256;
            int r = c >> 3, q = c & 7;
            cp_async16(bs + r * T_STRIDE + q * 8,
                       W + (size_t)(n0 + r) * KD + kbase + q * 8, true);
        }
    };

    #pragma unroll
    for (int s = 0; s < STAGES - 1; s++) {
        if (s < KT) issue(s, s);
        asm volatile("cp.async.commit_group;");
    }

    int wid = tid >> 5, lane = tid & 31;
    int g = lane >> 2, t = lane & 3;
    int wm = (wid >> 1) * 32;   // 4x2 warp grid, 32x64 warp tiles
    int wn = (wid & 1) * 64;

    // ldmatrix per-lane row addressing:
    int sub = lane >> 3, r8 = lane & 7;
    int a_off = (wm + (sub & 1) * 8 + r8) * T_STRIDE + (sub >> 1) * 8;
    int b_off = (wn + (sub >> 1) * 8 + r8) * T_STRIDE + (sub & 1) * 8;

    float acc[2][8][4];
    #pragma unroll
    for (int i = 0; i < 2; i++)
        #pragma unroll
        for (int j = 0; j < 8; j++)
            #pragma unroll
            for (int q = 0; q < 4; q++) acc[i][j][q] = 0.f;

    for (int kt = 0; kt < KT; kt++) {
        asm volatile("cp.async.wait_group %0;" :: "n"(STAGES - 2));
        __syncthreads();

        int nstage = kt + STAGES - 1;
        if (nstage < KT) issue(nstage, nstage % STAGES);
        asm volatile("cp.async.commit_group;");

        int st = kt % STAGES;
        uint32_t as_base = (uint32_t)__cvta_generic_to_shared(As + st * TILE_H) + a_off * 2;
        uint32_t bs_base = (uint32_t)__cvta_generic_to_shared(Bs + st * TILE_H) + b_off * 2;

        // double-buffered fragments: LDSM(ks+1) issues before mma(ks)
        uint32_t af[2][2][4], bf[2][8][2];

        auto load_frag = [&](int ks, uint32_t afr[2][4], uint32_t bfr[8][2]) {
            #pragma unroll
            for (int i = 0; i < 2; i++)
                ldsm_x4(afr[i][0], afr[i][1], afr[i][2], afr[i][3],
                        as_base + (i * 16 * T_STRIDE + ks * 16) * 2);
            #pragma unroll
            for (int jp = 0; jp < 4; jp++)
                ldsm_x4(bfr[2*jp][0], bfr[2*jp][1], bfr[2*jp+1][0], bfr[2*jp+1][1],
                        bs_base + (jp * 16 * T_STRIDE + ks * 16) * 2);
        };

        load_frag(0, af[0], bf[0]);
        #pragma unroll
        for (int ks = 0; ks < TKK / 16; ks++) {
            int cur = ks & 1, nxt = cur ^ 1;
            if (ks < TKK / 16 - 1) load_frag(ks + 1, af[nxt], bf[nxt]);
            #pragma unroll
            for (int i = 0; i < 2; i++)
                #pragma unroll
                for (int j = 0; j < 8; j++)
                    mma_f16(acc[i][j], af[cur][i], bf[cur][j]);
        }
    }

    // epilogue
    const float* bb = Ball + (size_t)e * ND + n0;
    #pragma unroll
    for (int i = 0; i < 2; i++) {
        int r0 = wm + i * 16 + g;
        int r1 = r0 + 8;
        int a0 = rows[r0], a1 = rows[r1];
        #pragma unroll
        for (int j = 0; j < 8; j++) {
            int col = wn + j * 8 + t * 2;
            float bx = bb[col], by = bb[col + 1];
            if (UP) {
                if (a0 >= 0) {
                    float v0 = gelu_tanh(acc[i][j][0] + bx);
                    float v1 = gelu_tanh(acc[i][j][1] + by);
                    *(__half2*)(g_hh + (size_t)a0 * HID + n0 + col) = __floats2half2_rn(v0, v1);
                }
                if (a1 >= 0) {
                    float v2 = gelu_tanh(acc[i][j][2] + bx);
                    float v3 = gelu_tanh(acc[i][j][3] + by);
                    *(__half2*)(g_hh + (size_t)a1 * HID + n0 + col) = __floats2half2_rn(v2, v3);
                }
            } else {
                if (a0 >= 0)
                    *(float2*)(g_y + (size_t)a0 * DIM + n0 + col) =
                        make_float2(acc[i][j][0] + bx, acc[i][j][1] + by);
                if (a1 >= 0)
                    *(float2*)(g_y + (size_t)a1 * DIM + n0 + col) =
                        make_float2(acc[i][j][2] + bx, acc[i][j][3] + by);
            }
        }
    }
}

// ---------------- kernel: deterministic weighted combine ----------------
__global__ __launch_bounds__(256) void combine_kernel(float* __restrict__ out) {
    int t = blockIdx.x;
    float w0 = g_topk_w[t * TOPK + 0];
    float w1 = g_topk_w[t * TOPK + 1];
    const float4* y0 = (const float4*)(g_y + (size_t)(t * TOPK + 0) * DIM);
    const float4* y1 = (const float4*)(g_y + (size_t)(t * TOPK + 1) * DIM);
    float4* o = (float4*)(out + (size_t)t * DIM);
    for (int d = threadIdx.x; d < DIM / 4; d += 256) {
        float4 a = y0[d], b = y1[d];
        float4 r;
        r.x = w0 * a.x + w1 * b.x;
        r.y = w0 * a.y + w1 * b.y;
        r.z = w0 * a.z + w1 * b.z;
        r.w = w0 * a.w + w1 * b.w;
        o[d] = r;
    }
}

// ---------------- launch ----------------
extern "C" void kernel_launch(void* const* d_in, const int* in_sizes, int n_in,
                              void* d_out, int out_size)
{
    const float* x  = (const float*)d_in[0];
    const float* rw = (const float*)d_in[1];
    const float* rb = (const float*)d_in[2];
    const float* wu = (const float*)d_in[3];
    const float* bu = (const float*)d_in[4];
    const float* wd = (const float*)d_in[5];
    const float* bd = (const float*)d_in[6];

    float* out       = (float*)d_out;
    float* out_y     = out;
    float* out_aux   = out + (size_t)NTOK * DIM;
    float* out_probs = out_aux + 1;

    cudaFuncSetAttribute(mma_gemm_kernel<true>,
        cudaFuncAttributeMaxDynamicSharedMemorySize, SMEM_BYTES);
    cudaFuncSetAttribute(mma_gemm_kernel<false>,
        cudaFuncAttributeMaxDynamicSharedMemorySize, SMEM_BYTES);

    __half* d_wuh = nullptr; cudaGetSymbolAddress((void**)&d_wuh, g_wuh);
    __half* d_wdh = nullptr; cudaGetSymbolAddress((void**)&d_wdh, g_wdh);

    // launch order chosen so the up-GEMM is the 4th launch (ncu captures #4)
    cvt_x_kernel<<<1184, 256>>>((const float4*)x, NTOK * DIM / 4);       // 1 (+zero)
    trans_cvt_fused_kernel<<<65536, 256>>>(wu, wd, d_wuh, d_wdh);        // 2
    router_kernel<<<NTOK, 256>>>(x, rw, rb, out_probs);                  // 3

    dim3 gu(HID / TN, CAP / TM, NE);
    mma_gemm_kernel<true><<<gu, 256, SMEM_BYTES>>>(bu);                  // 4 <- profiled

    aux_kernel<<<1, 32>>>(out_aux);                                      // 5

    dim3 gd(DIM / TN, CAP / TM, NE);
    mma_gemm_kernel<false><<<gd, 256, SMEM_BYTES>>>(bd);                 // 6

    combine_kernel<<<NTOK, 256>>>(out_y);                                // 7
}

// round 11
// speedup vs baseline: 2.1530x; 1.0124x over previous
#include <cuda_runtime.h>
#include <cuda_fp16.h>
#include <math.h>
#include <cstdint>

#define NTOK 8192      // B*S
#define DIM  1024      // d_model
#define NE   8         // experts
#define TOPK 2
#define HID  4096      // expert hidden
#define NA   (NTOK*TOPK)   // 16384 assignments
#define CAP  NA            // per-expert bucket capacity (worst case)

// ---------------- device scratch (no allocations allowed) ----------------
__device__ int    g_bucket[NE*CAP];
__device__ int    g_cursor[NE];
__device__ float  g_prob_sum[NE];
__device__ float  g_topk_w[NA];
__device__ float  g_y[(size_t)NA*DIM];            // 67 MB
__device__ __half g_xh[(size_t)NTOK*DIM];         // fp16 x, 16.8 MB
__device__ __half g_wuh[(size_t)NE*HID*DIM];      // fp16 w_up^T  [e][n][k], 67 MB
__device__ __half g_wdh[(size_t)NE*DIM*HID];      // fp16 w_down^T[e][n][k], 67 MB
__device__ __half g_hh[(size_t)NA*HID];           // fp16 activations, 134 MB

// ---------------- kernel 1: convert x to fp16 (+ zero accumulators) -------
__global__ __launch_bounds__(256) void cvt_x_kernel(const float4* __restrict__ src, int n4) {
    if (blockIdx.x == 0 && threadIdx.x < NE) {
        g_cursor[threadIdx.x] = 0;
        g_prob_sum[threadIdx.x] = 0.f;
    }
    int stride = gridDim.x * blockDim.x;
    for (int i = blockIdx.x * blockDim.x + threadIdx.x; i < n4; i += stride) {
        float4 v = src[i];
        __half2 h01 = __floats2half2_rn(v.x, v.y);
        __half2 h23 = __floats2half2_rn(v.z, v.w);
        ((uint2*)g_xh)[i] = make_uint2(*(uint32_t*)&h01, *(uint32_t*)&h23);
    }
}

// ---------------- kernel 2: fused transpose+convert of both weights -------
__global__ __launch_bounds__(256) void trans_cvt_fused_kernel(
    const float* __restrict__ wu, const float* __restrict__ wd,
    __half* __restrict__ wuh, __half* __restrict__ wdh)
{
    __shared__ float tile[32][33];
    int bid = blockIdx.x;
    bool up = bid < 32768;
    int b  = up ? bid : bid - 32768;
    int e  = b >> 12;          // /4096 tiles per expert
    int r  = b & 4095;
    int KD = up ? DIM : HID;
    int ND = up ? HID : DIM;
    int xT = ND >> 5;
    int n0 = (r % xT) << 5;
    int k0 = (r / xT) << 5;
    const float* src = (up ? wu : wd) + (size_t)e * KD * ND;
    __half* dst      = (up ? wuh : wdh) + (size_t)e * ND * KD;
    int tx = threadIdx.x & 31, ty = threadIdx.x >> 5;
    #pragma unroll
    for (int i = ty; i < 32; i += 8)
        tile[i][tx] = src[(size_t)(k0 + i) * ND + n0 + tx];
    __syncthreads();
    #pragma unroll
    for (int i = ty; i < 32; i += 8)
        dst[(size_t)(n0 + i) * KD + k0 + tx] = __float2half(tile[tx][i]);
}

// ---------------- kernel 3: router ----------------
__global__ __launch_bounds__(256) void router_kernel(
    const float* __restrict__ x, const float* __restrict__ rw,
    const float* __restrict__ rb, float* __restrict__ probs_out)
{
    int t   = blockIdx.x;
    int tid = threadIdx.x;
    const float* xr = x + (size_t)t * DIM;

    float acc[NE];
    #pragma unroll
    for (int e = 0; e < NE; e++) acc[e] = 0.f;

    for (int d = tid; d < DIM; d += 256) {
        float xv = xr[d];
        const float* w = rw + (size_t)d * NE;
        #pragma unroll
        for (int e = 0; e < NE; e++) acc[e] += xv * w[e];
    }
    #pragma unroll
    for (int e = 0; e < NE; e++) {
        #pragma unroll
        for (int off = 16; off > 0; off >>= 1)
            acc[e] += __shfl_down_sync(0xffffffffu, acc[e], off);
    }
    __shared__ float wsum[8][NE];
    int warp = tid >> 5, lane = tid & 31;
    if (lane == 0) {
        #pragma unroll
        for (int e = 0; e < NE; e++) wsum[warp][e] = acc[e];
    }
    __syncthreads();

    if (tid == 0) {
        float lg[NE];
        #pragma unroll
        for (int e = 0; e < NE; e++) {
            float s = rb[e];
            #pragma unroll
            for (int w = 0; w < 8; w++) s += wsum[w][e];
            lg[e] = s;
        }
        float mx = lg[0];
        #pragma unroll
        for (int e = 1; e < NE; e++) mx = fmaxf(mx, lg[e]);
        float p[NE], den = 0.f;
        #pragma unroll
        for (int e = 0; e < NE; e++) { p[e] = expf(lg[e] - mx); den += p[e]; }
        float inv = 1.f / den;
        #pragma unroll
        for (int e = 0; e < NE; e++) {
            p[e] *= inv;
            probs_out[(size_t)t * NE + e] = p[e];
            atomicAdd(&g_prob_sum[e], p[e]);
        }
        int i0 = 0;
        #pragma unroll
        for (int e = 1; e < NE; e++) if (lg[e] > lg[i0]) i0 = e;
        int i1 = -1;
        #pragma unroll
        for (int e = 0; e < NE; e++)
            if (e != i0 && (i1 < 0 || lg[e] > lg[i1])) i1 = e;
        float e1 = expf(lg[i1] - lg[i0]);
        float p0 = 1.f / (1.f + e1);
        float p1 = e1 * p0;

        int a0 = t * TOPK + 0, a1 = t * TOPK + 1;
        g_topk_w[a0] = p0;
        g_topk_w[a1] = p1;
        int s0 = atomicAdd(&g_cursor[i0], 1);
        g_bucket[i0 * CAP + s0] = a0;
        int s1 = atomicAdd(&g_cursor[i1], 1);
        g_bucket[i1 * CAP + s1] = a1;
    }
}

// ---------------- kernel: aux loss ----------------
__global__ void aux_kernel(float* __restrict__ out_aux) {
    if (threadIdx.x == 0) {
        float s = 0.f;
        #pragma unroll
        for (int e = 0; e < NE; e++)
            s += ((float)g_cursor[e] / (float)NA) * (g_prob_sum[e] / (float)NTOK);
        *out_aux = (float)NE * s * 0.01f;
    }
}

// ---------------- fp16 tensor-core grouped GEMM ----------------
// 256 threads, 8 warps (4x2 grid of 32x64 warp tiles), m16n8k16 fp16 mma,
// ldmatrix.x4, TKK=64 slabs, 3-stage cp.async, 2 CTAs/SM.
// Inner loop interleaves LDSM and mma at jp granularity: per 4 mmas, one
// prefetch LDSM issues, keeping crossbar and tensor pipe busy concurrently.
#define TM 128
#define TN 128
#define TKK 64
#define STAGES 3
#define T_STRIDE 72    // fp16/row (144B); LDSM 8-row phase hits all 32 banks once
#define TILE_H (TM*T_STRIDE)
#define SMEM_BYTES (STAGES*TILE_H*2*2 + TM*4)

__device__ __forceinline__ float gelu_tanh(float v) {
    float c = v * v * v;
    return 0.5f * v * (1.f + tanhf(0.7978845608028654f * (v + 0.044715f * c)));
}

__device__ __forceinline__ void mma_f16(float* c, const uint32_t* a, const uint32_t* b) {
    asm volatile(
        "mma.sync.aligned.m16n8k16.row.col.f32.f16.f16.f32 "
        "{%0,%1,%2,%3}, {%4,%5,%6,%7}, {%8,%9}, {%0,%1,%2,%3};"
        : "+f"(c[0]), "+f"(c[1]), "+f"(c[2]), "+f"(c[3])
        : "r"(a[0]), "r"(a[1]), "r"(a[2]), "r"(a[3]), "r"(b[0]), "r"(b[1]));
}

__device__ __forceinline__ void ldsm_x4(uint32_t& r0, uint32_t& r1, uint32_t& r2, uint32_t& r3,
                                        uint32_t addr) {
    asm volatile("ldmatrix.sync.aligned.m8n8.x4.shared.b16 {%0,%1,%2,%3}, [%4];"
                 : "=r"(r0), "=r"(r1), "=r"(r2), "=r"(r3) : "r"(addr));
}

__device__ __forceinline__ void cp_async16(void* dst, const void* src, bool pred) {
    uint32_t d = (uint32_t)__cvta_generic_to_shared(dst);
    int sz = pred ? 16 : 0;
    asm volatile("cp.async.cg.shared.global [%0], [%1], 16, %2;\n"
                 :: "r"(d), "l"(src), "r"(sz));
}

// UP:  A = gathered g_xh rows, B = g_wuh[e] [HID][DIM], epilogue = gelu -> g_hh (fp16)
// DN:  A = gathered g_hh rows, B = g_wdh[e] [DIM][HID], epilogue = +bias -> g_y (fp32)
template<bool UP>
__global__ __launch_bounds__(256, 2)
void mma_gemm_kernel(const float* __restrict__ Ball)
{
    constexpr int KD = UP ? DIM : HID;
    constexpr int ND = UP ? HID : DIM;
    constexpr int KT = KD / TKK;

    int e   = blockIdx.z;
    int cnt = g_cursor[e];
    int m0  = blockIdx.y * TM;
    if (m0 >= cnt) return;
    int n0  = blockIdx.x * TN;

    extern __shared__ __half smem[];
    __half* As = smem;                         // [STAGES][TM][T_STRIDE]
    __half* Bs = smem + STAGES * TILE_H;       // [STAGES][TN][T_STRIDE]
    int*   rows = (int*)(smem + 2 * STAGES * TILE_H);

    int tid = threadIdx.x;
    if (tid < TM) {
        int m = m0 + tid;
        rows[tid] = (m < cnt) ? g_bucket[e * CAP + m] : -1;
    }
    __syncthreads();

    const __half* W = (UP ? g_wuh : g_wdh) + (size_t)e * (size_t)ND * KD;
    const __half* Abase = UP ? (const __half*)g_xh : (const __half*)g_hh;

    auto issue = [&](int kt, int stage) {
        __half* as = As + stage * TILE_H;
        __half* bs = Bs + stage * TILE_H;
        int kbase = kt * TKK;
        #pragma unroll
        for (int i = 0; i < 4; i++) {          // A: 128 rows x 8 chunks of 16B
            int c = tid + i * 256;
            int r = c >> 3, q = c & 7;
            int a = rows[r];
            bool pred = (a >= 0);
            const __half* src = Abase +
                (UP ? (size_t)(pred ? (a >> 1) : 0) * DIM
                    : (size_t)(pred ? a : 0) * HID) + kbase + q * 8;
            cp_async16(as + r * T_STRIDE + q * 8, src, pred);
        }
        #pragma unroll
        for (int i = 0; i < 4; i++) {          // B: 128 n-rows x 8 chunks
            int c = tid + i * 256;
            int r = c >> 3, q = c & 7;
            cp_async16(bs + r * T_STRIDE + q * 8,
                       W + (size_t)(n0 + r) * KD + kbase + q * 8, true);
        }
    };

    #pragma unroll
    for (int s = 0; s < STAGES - 1; s++) {
        if (s < KT) issue(s, s);
        asm volatile("cp.async.commit_group;");
    }

    int wid = tid >> 5, lane = tid & 31;
    int g = lane >> 2, t = lane & 3;
    int wm = (wid >> 1) * 32;   // 4x2 warp grid, 32x64 warp tiles
    int wn = (wid & 1) * 64;

    // ldmatrix per-lane row addressing:
    int sub = lane >> 3, r8 = lane & 7;
    int a_off = (wm + (sub & 1) * 8 + r8) * T_STRIDE + (sub >> 1) * 8;
    int b_off = (wn + (sub >> 1) * 8 + r8) * T_STRIDE + (sub & 1) * 8;

    float acc[2][8][4];
    #pragma unroll
    for (int i = 0; i < 2; i++)
        #pragma unroll
        for (int j = 0; j < 8; j++)
            #pragma unroll
            for (int q = 0; q < 4; q++) acc[i][j][q] = 0.f;

    for (int kt = 0; kt < KT; kt++) {
        asm volatile("cp.async.wait_group %0;" :: "n"(STAGES - 2));
        __syncthreads();

        int nstage = kt + STAGES - 1;
        if (nstage < KT) issue(nstage, nstage % STAGES);
        asm volatile("cp.async.commit_group;");

        int st = kt % STAGES;
        uint32_t as_base = (uint32_t)__cvta_generic_to_shared(As + st * TILE_H) + a_off * 2;
        uint32_t bs_base = (uint32_t)__cvta_generic_to_shared(Bs + st * TILE_H) + b_off * 2;

        uint32_t af[2][4];      // A fragments for current ks
        uint32_t bf[2][2][2];   // B pair double-buffer: [buf][jj][reg]

        // prologue: B pair (ks=0, jp=0)
        ldsm_x4(bf[0][0][0], bf[0][0][1], bf[0][1][0], bf[0][1][1], bs_base);

        #pragma unroll
        for (int ks = 0; ks < TKK / 16; ks++) {
            // A fragments for this ks (2 LDSM)
            #pragma unroll
            for (int i = 0; i < 2; i++)
                ldsm_x4(af[i][0], af[i][1], af[i][2], af[i][3],
                        as_base + (i * 16 * T_STRIDE + ks * 16) * 2);
            #pragma unroll
            for (int jp = 0; jp < 4; jp++) {
                int cur = jp & 1, nxt = cur ^ 1;
                // prefetch next B pair (same ks, jp+1; or next ks, jp=0)
                bool more = (jp < 3) || (ks < TKK / 16 - 1);
                int njp = (jp < 3) ? jp + 1 : 0;
                int nks = (jp < 3) ? ks : ks + 1;
                if (more)
                    ldsm_x4(bf[nxt][0][0], bf[nxt][0][1], bf[nxt][1][0], bf[nxt][1][1],
                            bs_base + (njp * 16 * T_STRIDE + nks * 16) * 2);
                // 4 mmas fed from current B pair
                mma_f16(acc[0][2*jp    ], af[0], bf[cur][0]);
                mma_f16(acc[0][2*jp + 1], af[0], bf[cur][1]);
                mma_f16(acc[1][2*jp    ], af[1], bf[cur][0]);
                mma_f16(acc[1][2*jp + 1], af[1], bf[cur][1]);
            }
        }
    }

    // epilogue
    const float* bb = Ball + (size_t)e * ND + n0;
    #pragma unroll
    for (int i = 0; i < 2; i++) {
        int r0 = wm + i * 16 + g;
        int r1 = r0 + 8;
        int a0 = rows[r0], a1 = rows[r1];
        #pragma unroll
        for (int j = 0; j < 8; j++) {
            int col = wn + j * 8 + t * 2;
            float bx = bb[col], by = bb[col + 1];
            if (UP) {
                if (a0 >= 0) {
                    float v0 = gelu_tanh(acc[i][j][0] + bx);
                    float v1 = gelu_tanh(acc[i][j][1] + by);
                    *(__half2*)(g_hh + (size_t)a0 * HID + n0 + col) = __floats2half2_rn(v0, v1);
                }
                if (a1 >= 0) {
                    float v2 = gelu_tanh(acc[i][j][2] + bx);
                    float v3 = gelu_tanh(acc[i][j][3] + by);
                    *(__half2*)(g_hh + (size_t)a1 * HID + n0 + col) = __floats2half2_rn(v2, v3);
                }
            } else {
                if (a0 >= 0)
                    *(float2*)(g_y + (size_t)a0 * DIM + n0 + col) =
                        make_float2(acc[i][j][0] + bx, acc[i][j][1] + by);
                if (a1 >= 0)
                    *(float2*)(g_y + (size_t)a1 * DIM + n0 + col) =
                        make_float2(acc[i][j][2] + bx, acc[i][j][3] + by);
            }
        }
    }
}

// ---------------- kernel: deterministic weighted combine ----------------
__global__ __launch_bounds__(256) void combine_kernel(float* __restrict__ out) {
    int t = blockIdx.x;
    float w0 = g_topk_w[t * TOPK + 0];
    float w1 = g_topk_w[t * TOPK + 1];
    const float4* y0 = (const float4*)(g_y + (size_t)(t * TOPK + 0) * DIM);
    const float4* y1 = (const float4*)(g_y + (size_t)(t * TOPK + 1) * DIM);
    float4* o = (float4*)(out + (size_t)t * DIM);
    for (int d = threadIdx.x; d < DIM / 4; d += 256) {
        float4 a = y0[d], b = y1[d];
        float4 r;
        r.x = w0 * a.x + w1 * b.x;
        r.y = w0 * a.y + w1 * b.y;
        r.z = w0 * a.z + w1 * b.z;
        r.w = w0 * a.w + w1 * b.w;
        o[d] = r;
    }
}

// ---------------- launch ----------------
extern "C" void kernel_launch(void* const* d_in, const int* in_sizes, int n_in,
                              void* d_out, int out_size)
{
    const float* x  = (const float*)d_in[0];
    const float* rw = (const float*)d_in[1];
    const float* rb = (const float*)d_in[2];
    const float* wu = (const float*)d_in[3];
    const float* bu = (const float*)d_in[4];
    const float* wd = (const float*)d_in[5];
    const float* bd = (const float*)d_in[6];

    float* out       = (float*)d_out;
    float* out_y     = out;
    float* out_aux   = out + (size_t)NTOK * DIM;
    float* out_probs = out_aux + 1;

    cudaFuncSetAttribute(mma_gemm_kernel<true>,
        cudaFuncAttributeMaxDynamicSharedMemorySize, SMEM_BYTES);
    cudaFuncSetAttribute(mma_gemm_kernel<false>,
        cudaFuncAttributeMaxDynamicSharedMemorySize, SMEM_BYTES);

    __half* d_wuh = nullptr; cudaGetSymbolAddress((void**)&d_wuh, g_wuh);
    __half* d_wdh = nullptr; cudaGetSymbolAddress((void**)&d_wdh, g_wdh);

    // launch order chosen so the up-GEMM is the 4th launch (ncu captures #4)
    cvt_x_kernel<<<1184, 256>>>((const float4*)x, NTOK * DIM / 4);       // 1 (+zero)
    trans_cvt_fused_kernel<<<65536, 256>>>(wu, wd, d_wuh, d_wdh);        // 2
    router_kernel<<<NTOK, 256>>>(x, rw, rb, out_probs);                  // 3

    dim3 gu(HID / TN, CAP / TM, NE);
    mma_gemm_kernel<true><<<gu, 256, SMEM_BYTES>>>(bu);                  // 4 <- profiled

    aux_kernel<<<1, 32>>>(out_aux);                                      // 5

    dim3 gd(DIM / TN, CAP / TM, NE);
    mma_gemm_kernel<false><<<gd, 256, SMEM_BYTES>>>(bd);                 // 6

    combine_kernel<<<NTOK, 256>>>(out_y);                                // 7
}

// round 12
// speedup vs baseline: 2.2353x; 1.0382x over previous
#include <cuda_runtime.h>
#include <cuda_fp16.h>
#include <math.h>
#include <cstdint>

#define NTOK 8192      // B*S
#define DIM  1024      // d_model
#define NE   8         // experts
#define TOPK 2
#define HID  4096      // expert hidden
#define NA   (NTOK*TOPK)   // 16384 assignments
#define CAP  NA            // per-expert bucket capacity (worst case)

// ---------------- device scratch (no allocations allowed) ----------------
__device__ int    g_bucket[NE*CAP];
__device__ int    g_cursor[NE];
__device__ float  g_prob_sum[NE];
__device__ float  g_topk_w[NA];
__device__ __half g_xh[(size_t)NTOK*DIM];         // fp16 x, 16.8 MB
__device__ __half g_wuh[(size_t)NE*DIM*HID];      // fp16 w_up  [e][k][n] (native), 67 MB
__device__ __half g_wdh[(size_t)NE*HID*DIM];      // fp16 w_down[e][k][n] (native), 67 MB
__device__ __half g_hh[(size_t)NA*HID];           // fp16 activations, 134 MB

// ---------------- kernel 1: cvt x to fp16 + zero output + zero counters ---
__global__ __launch_bounds__(256) void cvt_x_kernel(const float4* __restrict__ src, int n4,
                                                    float4* __restrict__ out_y, int o4) {
    if (blockIdx.x == 0 && threadIdx.x < NE) {
        g_cursor[threadIdx.x] = 0;
        g_prob_sum[threadIdx.x] = 0.f;
    }
    int stride = gridDim.x * blockDim.x;
    int idx0 = blockIdx.x * blockDim.x + threadIdx.x;
    for (int i = idx0; i < n4; i += stride) {
        float4 v = src[i];
        __half2 h01 = __floats2half2_rn(v.x, v.y);
        __half2 h23 = __floats2half2_rn(v.z, v.w);
        ((uint2*)g_xh)[i] = make_uint2(*(uint32_t*)&h01, *(uint32_t*)&h23);
    }
    float4 z = make_float4(0.f, 0.f, 0.f, 0.f);
    for (int i = idx0; i < o4; i += stride)
        out_y[i] = z;
}

// ---------------- kernel 2: straight fp32->fp16 cvt of both weights -------
__global__ __launch_bounds__(256) void cvt_w_kernel(
    const float4* __restrict__ wu, const float4* __restrict__ wd, int n4each)
{
    int stride = gridDim.x * blockDim.x;
    for (int i = blockIdx.x * blockDim.x + threadIdx.x; i < 2 * n4each; i += stride) {
        bool up = i < n4each;
        int j = up ? i : i - n4each;
        float4 v = up ? wu[j] : wd[j];
        __half2 h01 = __floats2half2_rn(v.x, v.y);
        __half2 h23 = __floats2half2_rn(v.z, v.w);
        uint2 p = make_uint2(*(uint32_t*)&h01, *(uint32_t*)&h23);
        if (up) ((uint2*)g_wuh)[j] = p;
        else    ((uint2*)g_wdh)[j] = p;
    }
}

// ---------------- kernel 3: router ----------------
__global__ __launch_bounds__(256) void router_kernel(
    const float* __restrict__ x, const float* __restrict__ rw,
    const float* __restrict__ rb, float* __restrict__ probs_out)
{
    int t   = blockIdx.x;
    int tid = threadIdx.x;
    const float* xr = x + (size_t)t * DIM;

    float acc[NE];
    #pragma unroll
    for (int e = 0; e < NE; e++) acc[e] = 0.f;

    for (int d = tid; d < DIM; d += 256) {
        float xv = xr[d];
        const float* w = rw + (size_t)d * NE;
        #pragma unroll
        for (int e = 0; e < NE; e++) acc[e] += xv * w[e];
    }
    #pragma unroll
    for (int e = 0; e < NE; e++) {
        #pragma unroll
        for (int off = 16; off > 0; off >>= 1)
            acc[e] += __shfl_down_sync(0xffffffffu, acc[e], off);
    }
    __shared__ float wsum[8][NE];
    int warp = tid >> 5, lane = tid & 31;
    if (lane == 0) {
        #pragma unroll
        for (int e = 0; e < NE; e++) wsum[warp][e] = acc[e];
    }
    __syncthreads();

    if (tid == 0) {
        float lg[NE];
        #pragma unroll
        for (int e = 0; e < NE; e++) {
            float s = rb[e];
            #pragma unroll
            for (int w = 0; w < 8; w++) s += wsum[w][e];
            lg[e] = s;
        }
        float mx = lg[0];
        #pragma unroll
        for (int e = 1; e < NE; e++) mx = fmaxf(mx, lg[e]);
        float p[NE], den = 0.f;
        #pragma unroll
        for (int e = 0; e < NE; e++) { p[e] = expf(lg[e] - mx); den += p[e]; }
        float inv = 1.f / den;
        #pragma unroll
        for (int e = 0; e < NE; e++) {
            p[e] *= inv;
            probs_out[(size_t)t * NE + e] = p[e];
            atomicAdd(&g_prob_sum[e], p[e]);
        }
        int i0 = 0;
        #pragma unroll
        for (int e = 1; e < NE; e++) if (lg[e] > lg[i0]) i0 = e;
        int i1 = -1;
        #pragma unroll
        for (int e = 0; e < NE; e++)
            if (e != i0 && (i1 < 0 || lg[e] > lg[i1])) i1 = e;
        float e1 = expf(lg[i1] - lg[i0]);
        float p0 = 1.f / (1.f + e1);
        float p1 = e1 * p0;

        int a0 = t * TOPK + 0, a1 = t * TOPK + 1;
        g_topk_w[a0] = p0;
        g_topk_w[a1] = p1;
        int s0 = atomicAdd(&g_cursor[i0], 1);
        g_bucket[i0 * CAP + s0] = a0;
        int s1 = atomicAdd(&g_cursor[i1], 1);
        g_bucket[i1 * CAP + s1] = a1;
    }
}

// ---------------- kernel: aux loss ----------------
__global__ void aux_kernel(float* __restrict__ out_aux) {
    if (threadIdx.x == 0) {
        float s = 0.f;
        #pragma unroll
        for (int e = 0; e < NE; e++)
            s += ((float)g_cursor[e] / (float)NA) * (g_prob_sum[e] / (float)NTOK);
        *out_aux = (float)NE * s * 0.01f;
    }
}

// ---------------- fp16 tensor-core grouped GEMM ----------------
// 256 threads, 8 warps (4x2 grid of 32x64 warp tiles), m16n8k16 fp16 mma.
// A tiles row-major [TM][72] (ldmatrix), B tiles K-MAJOR [TKK][136]
// (ldmatrix.trans, weights consumed in native layout — no transpose pass).
#define TM 128
#define TN 128
#define TKK 64
#define STAGES 3
#define A_STRIDE 72     // fp16/row (144B)
#define B_STRIDE 136    // fp16/row (272B); 8-row LDSM phase covers all 32 banks
#define A_TILE_H (TM*A_STRIDE)     // 9216 halfs
#define B_TILE_H (TKK*B_STRIDE)    // 8704 halfs
#define SMEM_BYTES (STAGES*(A_TILE_H+B_TILE_H)*2 + TM*4)

__device__ __forceinline__ float gelu_tanh(float v) {
    float c = v * v * v;
    return 0.5f * v * (1.f + tanhf(0.7978845608028654f * (v + 0.044715f * c)));
}

__device__ __forceinline__ void mma_f16(float* c, const uint32_t* a, const uint32_t* b) {
    asm volatile(
        "mma.sync.aligned.m16n8k16.row.col.f32.f16.f16.f32 "
        "{%0,%1,%2,%3}, {%4,%5,%6,%7}, {%8,%9}, {%0,%1,%2,%3};"
        : "+f"(c[0]), "+f"(c[1]), "+f"(c[2]), "+f"(c[3])
        : "r"(a[0]), "r"(a[1]), "r"(a[2]), "r"(a[3]), "r"(b[0]), "r"(b[1]));
}

__device__ __forceinline__ void ldsm_x4(uint32_t& r0, uint32_t& r1, uint32_t& r2, uint32_t& r3,
                                        uint32_t addr) {
    asm volatile("ldmatrix.sync.aligned.m8n8.x4.shared.b16 {%0,%1,%2,%3}, [%4];"
                 : "=r"(r0), "=r"(r1), "=r"(r2), "=r"(r3) : "r"(addr));
}

__device__ __forceinline__ void ldsm_x4_trans(uint32_t& r0, uint32_t& r1, uint32_t& r2, uint32_t& r3,
                                              uint32_t addr) {
    asm volatile("ldmatrix.sync.aligned.m8n8.x4.trans.shared.b16 {%0,%1,%2,%3}, [%4];"
                 : "=r"(r0), "=r"(r1), "=r"(r2), "=r"(r3) : "r"(addr));
}

__device__ __forceinline__ void cp_async16(void* dst, const void* src, bool pred) {
    uint32_t d = (uint32_t)__cvta_generic_to_shared(dst);
    int sz = pred ? 16 : 0;
    asm volatile("cp.async.cg.shared.global [%0], [%1], 16, %2;\n"
                 :: "r"(d), "l"(src), "r"(sz));
}

// UP:  A = gathered g_xh rows, B = g_wuh[e] [DIM][HID], epilogue = gelu -> g_hh (fp16)
// DN:  A = gathered g_hh rows, B = g_wdh[e] [HID][DIM], epilogue = atomicAdd(w*(acc+bias)) -> out
template<bool UP>
__global__ __launch_bounds__(256, 2)
void mma_gemm_kernel(const float* __restrict__ Ball, float* __restrict__ out_y)
{
    constexpr int KD = UP ? DIM : HID;
    constexpr int ND = UP ? HID : DIM;
    constexpr int KT = KD / TKK;

    int e   = blockIdx.z;
    int cnt = g_cursor[e];
    int m0  = blockIdx.y * TM;
    if (m0 >= cnt) return;
    int n0  = blockIdx.x * TN;

    extern __shared__ __half smem[];
    __half* As = smem;                              // [STAGES][TM][A_STRIDE]
    __half* Bs = smem + STAGES * A_TILE_H;          // [STAGES][TKK][B_STRIDE]
    int*   rows = (int*)(Bs + STAGES * B_TILE_H);

    int tid = threadIdx.x;
    if (tid < TM) {
        int m = m0 + tid;
        rows[tid] = (m < cnt) ? g_bucket[e * CAP + m] : -1;
    }
    __syncthreads();

    const __half* W = (UP ? g_wuh : g_wdh) + (size_t)e * (size_t)KD * ND;
    const __half* Abase = UP ? (const __half*)g_xh : (const __half*)g_hh;

    auto issue = [&](int kt, int stage) {
        __half* as = As + stage * A_TILE_H;
        __half* bs = Bs + stage * B_TILE_H;
        int kbase = kt * TKK;
        #pragma unroll
        for (int i = 0; i < 4; i++) {          // A: 128 rows x 8 chunks of 16B
            int c = tid + i * 256;
            int r = c >> 3, q = c & 7;
            int a = rows[r];
            bool pred = (a >= 0);
            const __half* src = Abase +
                (UP ? (size_t)(pred ? (a >> 1) : 0) * DIM
                    : (size_t)(pred ? a : 0) * HID) + kbase + q * 8;
            cp_async16(as + r * A_STRIDE + q * 8, src, pred);
        }
        #pragma unroll
        for (int i = 0; i < 4; i++) {          // B: 64 k-rows x 16 chunks (n contiguous)
            int c = tid + i * 256;
            int k = c >> 4, q = c & 15;
            cp_async16(bs + k * B_STRIDE + q * 8,
                       W + (size_t)(kbase + k) * ND + n0 + q * 8, true);
        }
    };

    #pragma unroll
    for (int s = 0; s < STAGES - 1; s++) {
        if (s < KT) issue(s, s);
        asm volatile("cp.async.commit_group;");
    }

    int wid = tid >> 5, lane = tid & 31;
    int g = lane >> 2, t = lane & 3;
    int wm = (wid >> 1) * 32;   // 4x2 warp grid, 32x64 warp tiles
    int wn = (wid & 1) * 64;

    int sub = lane >> 3, r8 = lane & 7;
    // A (row-major, non-trans): m0: rows wm..+7 k0 | m1: rows+8 k0 | m2: rows k8 | m3: rows+8 k8
    int a_off = (wm + (sub & 1) * 8 + r8) * A_STRIDE + (sub >> 1) * 8;
    // B (k-major, trans): m0: k0-7 ncol0 | m1: k8-15 ncol0 | m2: k0-7 ncol8 | m3: k8-15 ncol8
    int b_off = ((sub & 1) * 8 + r8) * B_STRIDE + wn + (sub >> 1) * 8;

    float acc[2][8][4];
    #pragma unroll
    for (int i = 0; i < 2; i++)
        #pragma unroll
        for (int j = 0; j < 8; j++)
            #pragma unroll
            for (int q = 0; q < 4; q++) acc[i][j][q] = 0.f;

    for (int kt = 0; kt < KT; kt++) {
        asm volatile("cp.async.wait_group %0;" :: "n"(STAGES - 2));
        __syncthreads();

        int nstage = kt + STAGES - 1;
        if (nstage < KT) issue(nstage, nstage % STAGES);
        asm volatile("cp.async.commit_group;");

        int st = kt % STAGES;
        uint32_t as_base = (uint32_t)__cvta_generic_to_shared(As + st * A_TILE_H) + a_off * 2;
        uint32_t bs_base = (uint32_t)__cvta_generic_to_shared(Bs + st * B_TILE_H) + b_off * 2;

        uint32_t af[2][4];      // A fragments for current ks
        uint32_t bf[2][2][2];   // B pair double-buffer: [buf][jj][reg]

        // prologue: B pair (ks=0, jp=0)
        ldsm_x4_trans(bf[0][0][0], bf[0][0][1], bf[0][1][0], bf[0][1][1], bs_base);

        #pragma unroll
        for (int ks = 0; ks < TKK / 16; ks++) {
            #pragma unroll
            for (int i = 0; i < 2; i++)
                ldsm_x4(af[i][0], af[i][1], af[i][2], af[i][3],
                        as_base + (i * 16 * A_STRIDE + ks * 16) * 2);
            #pragma unroll
            for (int jp = 0; jp < 4; jp++) {
                int cur = jp & 1, nxt = cur ^ 1;
                bool more = (jp < 3) || (ks < TKK / 16 - 1);
                int njp = (jp < 3) ? jp + 1 : 0;
                int nks = (jp < 3) ? ks : ks + 1;
                if (more)
                    ldsm_x4_trans(bf[nxt][0][0], bf[nxt][0][1], bf[nxt][1][0], bf[nxt][1][1],
                                  bs_base + (nks * 16 * B_STRIDE + njp * 16) * 2);
                mma_f16(acc[0][2*jp    ], af[0], bf[cur][0]);
                mma_f16(acc[0][2*jp + 1], af[0], bf[cur][1]);
                mma_f16(acc[1][2*jp    ], af[1], bf[cur][0]);
                mma_f16(acc[1][2*jp + 1], af[1], bf[cur][1]);
            }
        }
    }

    // epilogue
    const float* bb = Ball + (size_t)e * ND + n0;
    #pragma unroll
    for (int i = 0; i < 2; i++) {
        int r0 = wm + i * 16 + g;
        int r1 = r0 + 8;
        int a0 = rows[r0], a1 = rows[r1];
        if (UP) {
            #pragma unroll
            for (int j = 0; j < 8; j++) {
                int col = wn + j * 8 + t * 2;
                float bx = bb[col], by = bb[col + 1];
                if (a0 >= 0) {
                    float v0 = gelu_tanh(acc[i][j][0] + bx);
                    float v1 = gelu_tanh(acc[i][j][1] + by);
                    *(__half2*)(g_hh + (size_t)a0 * HID + n0 + col) = __floats2half2_rn(v0, v1);
                }
                if (a1 >= 0) {
                    float v2 = gelu_tanh(acc[i][j][2] + bx);
                    float v3 = gelu_tanh(acc[i][j][3] + by);
                    *(__half2*)(g_hh + (size_t)a1 * HID + n0 + col) = __floats2half2_rn(v2, v3);
                }
            }
        } else {
            float w0 = (a0 >= 0) ? g_topk_w[a0] : 0.f;
            float w1 = (a1 >= 0) ? g_topk_w[a1] : 0.f;
            float* o0 = out_y + (size_t)(a0 >> 1) * DIM + n0;
            float* o1 = out_y + (size_t)(a1 >> 1) * DIM + n0;
            #pragma unroll
            for (int j = 0; j < 8; j++) {
                int col = wn + j * 8 + t * 2;
                float bx = bb[col], by = bb[col + 1];
                if (a0 >= 0) {
                    atomicAdd(o0 + col,     w0 * (acc[i][j][0] + bx));
                    atomicAdd(o0 + col + 1, w0 * (acc[i][j][1] + by));
                }
                if (a1 >= 0) {
                    atomicAdd(o1 + col,     w1 * (acc[i][j][2] + bx));
                    atomicAdd(o1 + col + 1, w1 * (acc[i][j][3] + by));
                }
            }
        }
    }
}

// ---------------- launch ----------------
extern "C" void kernel_launch(void* const* d_in, const int* in_sizes, int n_in,
                              void* d_out, int out_size)
{
    const float* x  = (const float*)d_in[0];
    const float* rw = (const float*)d_in[1];
    const float* rb = (const float*)d_in[2];
    const float* wu = (const float*)d_in[3];
    const float* bu = (const float*)d_in[4];
    const float* wd = (const float*)d_in[5];
    const float* bd = (const float*)d_in[6];

    float* out       = (float*)d_out;
    float* out_y     = out;
    float* out_aux   = out + (size_t)NTOK * DIM;
    float* out_probs = out_aux + 1;

    cudaFuncSetAttribute(mma_gemm_kernel<true>,
        cudaFuncAttributeMaxDynamicSharedMemorySize, SMEM_BYTES);
    cudaFuncSetAttribute(mma_gemm_kernel<false>,
        cudaFuncAttributeMaxDynamicSharedMemorySize, SMEM_BYTES);

    // launch order keeps the up-GEMM at position 4 (ncu captures launch #4)
    cvt_x_kernel<<<1184, 256>>>((const float4*)x, NTOK * DIM / 4,
                                (float4*)out_y, NTOK * DIM / 4);          // 1
    cvt_w_kernel<<<2368, 256>>>((const float4*)wu, (const float4*)wd,
                                NE * DIM * HID / 4);                      // 2
    router_kernel<<<NTOK, 256>>>(x, rw, rb, out_probs);                   // 3

    dim3 gu(HID / TN, CAP / TM, NE);
    mma_gemm_kernel<true><<<gu, 256, SMEM_BYTES>>>(bu, out_y);            // 4 <- profiled

    aux_kernel<<<1, 32>>>(out_aux);                                       // 5

    dim3 gd(DIM / TN, CAP / TM, NE);
    mma_gemm_kernel<false><<<gd, 256, SMEM_BYTES>>>(bd, out_y);           // 6
}